// round 10
// baseline (speedup 1.0000x reference)
#include <cuda_runtime.h>
#include <math.h>

#define NB 2049
#define S_ 2048
#define W_ 64
#define D_ 300
#define M_ 100
#define H_ 8
#define D2_ 200
#define V_ 50000
#define RSQ 0.07071067811865475f   // 1/sqrt(200)

#define RPB 28                     // rows per LSTM block
#define RH 14                      // rows per thread-half
#define HTS 34                     // hT row stride (even -> 8B aligned pairs)

typedef unsigned long long u64;

__device__ __forceinline__ u64 pk2(float lo, float hi) {
    u64 r; asm("mov.b64 %0, {%1,%2};" : "=l"(r) : "f"(lo), "f"(hi)); return r;
}
__device__ __forceinline__ void upk2(u64 v, float& lo, float& hi) {
    asm("mov.b64 {%0,%1}, %2;" : "=f"(lo), "=f"(hi) : "l"(v));
}
__device__ __forceinline__ u64 ffma2(u64 a, u64 b, u64 c) {
    u64 d; asm("fma.rn.f32x2 %0, %1, %2, %3;" : "=l"(d) : "l"(a), "l"(b), "l"(c)); return d;
}

// ----------------------------- device scratch ------------------------------
__device__ float g_EW[V_ * 800];          // emb @ [w_ih_f | w_ih_b]^T
__device__ float g_hid[NB * D2_];         // [h_f | h_b]
__device__ float g_hv[D2_];
__device__ float g_logit[S_];
__device__ float g_prob[S_];
__device__ float g_att[S_ * D2_];
__device__ float g_Qa[H_ * S_ * D2_];
__device__ float g_Ka[H_ * S_ * D2_];
__device__ float g_Va[H_ * S_ * D2_];
__device__ float g_Qc[H_ * S_ * D2_];
__device__ float g_Kc[H_ * S_ * D2_];
__device__ float g_Vc[H_ * S_ * D2_];
__device__ float g_SC[33554432];          // 8 * 2048 * 2048 scores -> P in place
__device__ float g_mx[H_ * S_];
__device__ float g_iZ[H_ * S_];
__device__ float g_cat[S_ * H_ * D2_];    // out in cat layout [s][h*200+o]
__device__ float g_mh[S_ * D2_];
__device__ float g_fp[2 * 8 * D2_];
__device__ int   g_idx[2][S_];
__device__ int   g_n[2];

// ----------------------- f32x2 SGEMM (BM=128, BN=64) -----------------------
// C[M,N] = A[M,K] * op(B) (+ bias[bz*sBias+n]); transB: B is (N,K) row-major.
// limBr>=0: lim=g_n[limBr]; limRows/limCols skip tiles past lim; capK caps K.
// epi: 1 -> v*RSQ ; 2 -> (1-v)*RSQ.
#define BM 128
#define BN 64
#define BK 16
#define ASTR 264   // duplicated A row stride (floats)
#define BSTR 72

__global__ void sgemm(const float* __restrict__ A, int lda, long long sA,
                      const float* __restrict__ B, int ldb, long long sB, int transB,
                      float* __restrict__ C, int ldc, long long sC,
                      int M, int N, int K,
                      const float* __restrict__ bias, int sBias,
                      int limBr, int limRows, int limCols, int capK, int epi)
{
    int bz = blockIdx.z;
    int m0 = blockIdx.y * BM;
    int n0 = blockIdx.x * BN;
    if (limBr >= 0) {
        int lim = g_n[limBr];
        if (limRows && m0 >= lim) return;
        if (limCols && n0 >= lim) return;
        if (capK) { int kc = (lim + 15) & ~15; if (kc < K) K = kc; }
    }
    A += (long long)bz * sA;
    B += (long long)bz * sB;
    C += (long long)bz * sC;

    __shared__ __align__(16) float Asd[BK][ASTR];  // duplicated pairs (a,a)
    __shared__ __align__(16) float Bs[BK][BSTR];

    int tid = threadIdx.x;            // 256 threads
    int tr = tid >> 3;                // 0..31 -> 4 rows each
    int tc = tid & 7;                 // 0..7  -> 8 cols each
    u64 accp[4][4];
#pragma unroll
    for (int i = 0; i < 4; i++)
#pragma unroll
        for (int p = 0; p < 4; p++) accp[i][p] = 0ull;

    for (int k0 = 0; k0 < K; k0 += BK) {
        // stage A (128x16) duplicated
#pragma unroll
        for (int i = 0; i < 8; i++) {
            int e = tid + i * 256;
            int m = e >> 4, k = e & 15;
            int gm = m0 + m, gk = k0 + k;
            float v = (gm < M && gk < K) ? A[(long long)gm * lda + gk] : 0.f;
            *reinterpret_cast<float2*>(&Asd[k][2 * m]) = make_float2(v, v);
        }
        // stage B (64x16)
        if (transB) {
#pragma unroll
            for (int i = 0; i < 4; i++) {
                int e = tid + i * 256;
                int nn = e >> 4, k = e & 15;
                int gn = n0 + nn, gk = k0 + k;
                Bs[k][nn] = (gn < N && gk < K) ? B[(long long)gn * ldb + gk] : 0.f;
            }
        } else {
#pragma unroll
            for (int i = 0; i < 4; i++) {
                int e = tid + i * 256;
                int k = e >> 6, nn = e & 63;
                int gk = k0 + k, gn = n0 + nn;
                Bs[k][nn] = (gk < K && gn < N) ? B[(long long)gk * ldb + gn] : 0.f;
            }
        }
        __syncthreads();
#pragma unroll
        for (int k = 0; k < BK; k++) {
            ulonglong2 a01 = *reinterpret_cast<const ulonglong2*>(&Asd[k][8 * tr]);
            ulonglong2 a23 = *reinterpret_cast<const ulonglong2*>(&Asd[k][8 * tr + 4]);
            ulonglong2 b03 = *reinterpret_cast<const ulonglong2*>(&Bs[k][8 * tc]);
            ulonglong2 b47 = *reinterpret_cast<const ulonglong2*>(&Bs[k][8 * tc + 4]);
            u64 ad[4] = {a01.x, a01.y, a23.x, a23.y};
            u64 bp[4] = {b03.x, b03.y, b47.x, b47.y};
#pragma unroll
            for (int i = 0; i < 4; i++) {
                accp[i][0] = ffma2(ad[i], bp[0], accp[i][0]);
                accp[i][1] = ffma2(ad[i], bp[1], accp[i][1]);
                accp[i][2] = ffma2(ad[i], bp[2], accp[i][2]);
                accp[i][3] = ffma2(ad[i], bp[3], accp[i][3]);
            }
        }
        __syncthreads();
    }
#pragma unroll
    for (int i = 0; i < 4; i++) {
        int gm = m0 + tr * 4 + i;
        if (gm >= M) continue;
#pragma unroll
        for (int p = 0; p < 4; p++) {
            float v0, v1;
            upk2(accp[i][p], v0, v1);
            int gn0 = n0 + tc * 8 + 2 * p;
#pragma unroll
            for (int q = 0; q < 2; q++) {
                int gn = gn0 + q;
                if (gn >= N) continue;
                float v = q ? v1 : v0;
                if (bias) v += bias[bz * sBias + gn];
                if (epi == 1) v *= RSQ;
                else if (epi == 2) v = (1.f - v) * RSQ;
                C[(long long)gm * ldc + gn] = v;
            }
        }
    }
}

// ------------------------- fused all-timestep LSTM --------------------------
__global__ void lstm_all(const int* __restrict__ rsent, const int* __restrict__ body,
                         const float* __restrict__ whf, const float* __restrict__ whb,
                         const float* __restrict__ bihf, const float* __restrict__ bhhf,
                         const float* __restrict__ bihb, const float* __restrict__ bhhb)
{
    extern __shared__ float sh[];
    float* Wsh = sh;                        // [100][401]  Wsh[m*401+j] = whh[j][m]
    float* hT  = sh + 40100;                // [100][HTS]  hT[m*HTS+r]
    float* bcs = sh + 40100 + 100 * HTS;    // [400]
    int*   toks = (int*)(bcs + 400);        // [28]

    int dir = blockIdx.y;
    int n0 = blockIdx.x * RPB;
    int tid = threadIdx.x;                  // 256

    const float* wh = dir ? whb : whf;
    const float* bi = dir ? bihb : bihf;
    const float* bh = dir ? bhhb : bhhf;

    for (int e = tid; e < 40000; e += 256) {
        int j = e / 100, m = e - j * 100;
        Wsh[m * 401 + j] = wh[e];
    }
    for (int j = tid; j < 400; j += 256) bcs[j] = bi[j] + bh[j];
    for (int e = tid; e < 100 * HTS; e += 256) hT[e] = 0.f;
    __syncthreads();

    int m2 = tid & 127;
    int half = tid >> 7;
    int rbase = half * RH;
    bool act = (m2 < 100);

    float c[RH];
#pragma unroll
    for (int r = 0; r < RH; r++) c[r] = 0.f;

    for (int t = 0; t < 64; t++) {
        int w = dir ? (63 - t) : t;
        if (tid < RPB) {
            int n = n0 + tid;
            if (n >= NB) n = NB - 1;
            toks[tid] = (n == 0) ? rsent[w] : body[(n - 1) * W_ + w];
        }
        __syncthreads();

        u64 accp[4][7];
        if (act) {
#pragma unroll
            for (int g = 0; g < 4; g++) {
                int j = m2 + g * 100;
                float bj = bcs[j];
#pragma unroll
                for (int p = 0; p < 7; p++) {
                    float e0 = g_EW[(long long)toks[rbase + 2 * p]     * 800 + dir * 400 + j];
                    float e1 = g_EW[(long long)toks[rbase + 2 * p + 1] * 800 + dir * 400 + j];
                    accp[g][p] = pk2(bj + e0, bj + e1);
                }
            }
            for (int m = 0; m < 100; m++) {
                float w0 = Wsh[m * 401 + m2];
                float w1 = Wsh[m * 401 + m2 + 100];
                float w2 = Wsh[m * 401 + m2 + 200];
                float w3 = Wsh[m * 401 + m2 + 300];
                u64 wd0 = pk2(w0, w0), wd1 = pk2(w1, w1);
                u64 wd2 = pk2(w2, w2), wd3 = pk2(w3, w3);
                const u64* hp = reinterpret_cast<const u64*>(&hT[m * HTS + rbase]);
#pragma unroll
                for (int p = 0; p < 7; p++) {
                    u64 hv = hp[p];
                    accp[0][p] = ffma2(wd0, hv, accp[0][p]);
                    accp[1][p] = ffma2(wd1, hv, accp[1][p]);
                    accp[2][p] = ffma2(wd2, hv, accp[2][p]);
                    accp[3][p] = ffma2(wd3, hv, accp[3][p]);
                }
            }
        }
        __syncthreads();   // hT reads done before overwrite
        if (act) {
#pragma unroll
            for (int p = 0; p < 7; p++) {
                float gi0, gi1, gf0, gf1, gg0, gg1, go0, go1;
                upk2(accp[0][p], gi0, gi1);
                upk2(accp[1][p], gf0, gf1);
                upk2(accp[2][p], gg0, gg1);
                upk2(accp[3][p], go0, go1);
                int r0 = 2 * p, r1 = 2 * p + 1;
                float fi = 1.f / (1.f + expf(-gi0));
                float ff = 1.f / (1.f + expf(-gf0));
                float fo = 1.f / (1.f + expf(-go0));
                c[r0] = ff * c[r0] + fi * tanhf(gg0);
                hT[m2 * HTS + rbase + r0] = fo * tanhf(c[r0]);
                fi = 1.f / (1.f + expf(-gi1));
                ff = 1.f / (1.f + expf(-gf1));
                fo = 1.f / (1.f + expf(-go1));
                c[r1] = ff * c[r1] + fi * tanhf(gg1);
                hT[m2 * HTS + rbase + r1] = fo * tanhf(c[r1]);
            }
        }
        __syncthreads();
    }

    if (act) {
#pragma unroll
        for (int r = 0; r < RH; r++) {
            int n = n0 + rbase + r;
            if (n < NB) g_hid[n * D2_ + dir * M_ + m2] = hT[m2 * HTS + rbase + r];
        }
    }
}

// ----------------------------- sim / partition -----------------------------
__global__ void hv_k(const float* __restrict__ simw)
{
    int warp = threadIdx.x >> 5, lane = threadIdx.x & 31;
    int b = blockIdx.x * 32 + warp;
    if (b >= D2_) return;
    float a = 0.f;
    for (int i = lane; i < D2_; i += 32) a += g_hid[i] * simw[i * D2_ + b];
#pragma unroll
    for (int o = 16; o; o >>= 1) a += __shfl_down_sync(0xffffffffu, a, o);
    if (lane == 0) g_hv[b] = a;
}

__global__ void logits_k(const float* __restrict__ simb)
{
    __shared__ float hv[D2_];
    int tid = threadIdx.x;
    if (tid < D2_) hv[tid] = g_hv[tid];
    __syncthreads();
    int warp = tid >> 5, lane = tid & 31;
    int s = blockIdx.x * 8 + warp;
    const float* row = g_hid + (long long)(s + 1) * D2_;
    float a = 0.f;
    for (int b = lane; b < D2_; b += 32) a += hv[b] * row[b];
#pragma unroll
    for (int o = 16; o; o >>= 1) a += __shfl_down_sync(0xffffffffu, a, o);
    if (lane == 0) g_logit[s] = a + simb[0];
}

__global__ void softpart()
{
    __shared__ float sg[S_];
    __shared__ float redm[32];
    __shared__ float reds[32];
    __shared__ int cnt[1024];
    int tid = threadIdx.x;           // 1024
    for (int s = tid; s < S_; s += 1024) {
        float l = g_logit[s];
        sg[s] = 1.f / (1.f + expf(-l));
    }
    __syncthreads();
    float m = fmaxf(sg[tid], sg[tid + 1024]);
#pragma unroll
    for (int o = 16; o; o >>= 1) m = fmaxf(m, __shfl_xor_sync(0xffffffffu, m, o));
    if ((tid & 31) == 0) redm[tid >> 5] = m;
    __syncthreads();
    if (tid < 32) {
        float v = redm[tid];
#pragma unroll
        for (int o = 16; o; o >>= 1) v = fmaxf(v, __shfl_xor_sync(0xffffffffu, v, o));
        if (tid == 0) redm[0] = v;
    }
    __syncthreads();
    float mx = redm[0];
    float z = expf(sg[tid] - mx) + expf(sg[tid + 1024] - mx);
#pragma unroll
    for (int o = 16; o; o >>= 1) z += __shfl_xor_sync(0xffffffffu, z, o);
    if ((tid & 31) == 0) reds[tid >> 5] = z;
    __syncthreads();
    if (tid < 32) {
        float v = reds[tid];
#pragma unroll
        for (int o = 16; o; o >>= 1) v += __shfl_xor_sync(0xffffffffu, v, o);
        if (tid == 0) reds[0] = v;
    }
    __syncthreads();
    float invZ = 1.f / reds[0];
    for (int s = tid; s < S_; s += 1024) g_prob[s] = expf(sg[s] - mx) * invZ;

    int a = (sg[2 * tid] >= 0.5f) ? 1 : 0;
    int b = (sg[2 * tid + 1] >= 0.5f) ? 1 : 0;
    cnt[tid] = a + b;
    __syncthreads();
    for (int off = 1; off < 1024; off <<= 1) {
        int v = cnt[tid];
        int u = (tid >= off) ? cnt[tid - off] : 0;
        __syncthreads();
        cnt[tid] = v + u;
        __syncthreads();
    }
    int pre = (tid > 0) ? cnt[tid - 1] : 0;
    int tot = cnt[1023];
    int s0 = 2 * tid, s1 = 2 * tid + 1;
    if (a) g_idx[0][pre] = s0; else g_idx[1][s0 - pre] = s0;
    int pre1 = pre + a;
    if (b) g_idx[0][pre1] = s1; else g_idx[1][s1 - pre1] = s1;
    if (tid == 0) { g_n[0] = tot; g_n[1] = S_ - tot; }
}

__global__ void attend_k()
{
    int e = blockIdx.x * 256 + threadIdx.x;
    if (e >= S_ * D2_) return;
    int s = e / D2_;
    g_att[e] = g_prob[s] * g_hid[e + D2_];
}

// -------------------------- branch-local kernels ---------------------------
__global__ void compact(int br)
{
    int p = blockIdx.x;
    if (p >= g_n[br]) return;
    int src = g_idx[br][p];
    for (int e = threadIdx.x; e < H_ * D2_; e += 192) {
        int h = e / D2_, o = e - h * D2_;
        long long di = (long long)h * (S_ * D2_) + (long long)p * D2_ + o;
        long long si = (long long)h * (S_ * D2_) + (long long)src * D2_ + o;
        g_Qc[di] = g_Qa[si];
        g_Kc[di] = g_Ka[si];
        g_Vc[di] = g_Va[si];
    }
}

__global__ void colstats(int br)
{
    int n = g_n[br];
    int t = blockIdx.x * 128 + threadIdx.x;
    if (t >= n) return;
    int h = blockIdx.y;
    const float* base = g_SC + (long long)h * S_ * S_ + t;
    float m = -1e30f;
    for (int s = 0; s < n; s++) m = fmaxf(m, base[(long long)s * S_]);
    float z = 0.f;
    for (int s = 0; s < n; s++) z += expf(base[(long long)s * S_] - m);
    g_mx[h * S_ + t] = m;
    g_iZ[h * S_ + t] = 1.f / z;
}

__global__ void pnorm(int br)
{
    int n = g_n[br];
    int s = blockIdx.y;
    if (s >= n) return;
    int capn = (n + 15) & ~15;
    int t = blockIdx.x * 256 + threadIdx.x;
    if (t >= capn) return;
    int h = blockIdx.z;
    long long ix = (long long)h * S_ * S_ + (long long)s * S_ + t;
    float v = 0.f;
    if (t < n) v = expf(g_SC[ix] - g_mx[h * S_ + t]) * g_iZ[h * S_ + t];
    g_SC[ix] = v;
}

__global__ void featpart(const float* __restrict__ fw, int br)
{
    int n = g_n[br];
    int j = blockIdx.x;
    int ch = blockIdx.y;
    int per = (n + 7) / 8;
    int s0 = ch * per;
    int s1 = s0 + per; if (s1 > n) s1 = n;
    if (s0 > n) s0 = n;
    float acc = 0.f;
    const float* base = fw + (long long)j * (S_ * D2_);
    for (long long e = (long long)s0 * D2_ + threadIdx.x; e < (long long)s1 * D2_; e += 256)
        acc += g_mh[e] * base[e];
    __shared__ float red[8];
#pragma unroll
    for (int o = 16; o; o >>= 1) acc += __shfl_xor_sync(0xffffffffu, acc, o);
    if ((threadIdx.x & 31) == 0) red[threadIdx.x >> 5] = acc;
    __syncthreads();
    if (threadIdx.x < 8) {
        float v = red[threadIdx.x];
#pragma unroll
        for (int o = 4; o; o >>= 1) v += __shfl_xor_sync(0x000000ffu, v, o);
        if (threadIdx.x == 0) g_fp[(br * 8 + ch) * D2_ + j] = v;
    }
}

__global__ void finalize(const float* __restrict__ fb, float* __restrict__ out)
{
    int i = blockIdx.x * 256 + threadIdx.x;
    if (i >= 400) return;
    int br = i / 200, j = i - br * 200;
    float a = fb[j];
    for (int c = 0; c < 8; c++) a += g_fp[(br * 8 + c) * D2_ + j];
    out[i] = a;
}

// --------------------------------- launcher --------------------------------
extern "C" void kernel_launch(void* const* d_in, const int* in_sizes, int n_in,
                              void* d_out, int out_size)
{
    const int*   rsent = (const int*)d_in[0];
    const int*   body  = (const int*)d_in[1];
    const float* emb   = (const float*)d_in[2];
    const float* wihf  = (const float*)d_in[3];
    const float* whhf  = (const float*)d_in[4];
    const float* bihf  = (const float*)d_in[5];
    const float* bhhf  = (const float*)d_in[6];
    const float* wihb  = (const float*)d_in[7];
    const float* whhb  = (const float*)d_in[8];
    const float* bihb  = (const float*)d_in[9];
    const float* bhhb  = (const float*)d_in[10];
    const float* simw  = (const float*)d_in[11];
    const float* simb  = (const float*)d_in[12];
    const float* qw    = (const float*)d_in[13];
    const float* qb    = (const float*)d_in[14];
    const float* kw    = (const float*)d_in[15];
    const float* kb    = (const float*)d_in[16];
    const float* vw    = (const float*)d_in[17];
    const float* vb    = (const float*)d_in[18];
    const float* cw    = (const float*)d_in[19];
    const float* cb    = (const float*)d_in[20];
    const float* fw    = (const float*)d_in[21];
    const float* fb    = (const float*)d_in[22];
    float* out = (float*)d_out;

    float *pEW, *pAtt, *pQa, *pKa, *pVa, *pQc, *pKc, *pVc, *pSC, *pCat, *pMh;
    cudaGetSymbolAddress((void**)&pEW, g_EW);
    cudaGetSymbolAddress((void**)&pAtt, g_att);
    cudaGetSymbolAddress((void**)&pQa, g_Qa);
    cudaGetSymbolAddress((void**)&pKa, g_Ka);
    cudaGetSymbolAddress((void**)&pVa, g_Va);
    cudaGetSymbolAddress((void**)&pQc, g_Qc);
    cudaGetSymbolAddress((void**)&pKc, g_Kc);
    cudaGetSymbolAddress((void**)&pVc, g_Vc);
    cudaGetSymbolAddress((void**)&pSC, g_SC);
    cudaGetSymbolAddress((void**)&pCat, g_cat);
    cudaGetSymbolAddress((void**)&pMh, g_mh);

    // EW = emb @ w_ih^T  (per direction)
    dim3 ge(7, 391, 1);
    sgemm<<<ge, 256>>>(emb, 300, 0, wihf, 300, 0, 1, pEW,       800, 0,
                       V_, 400, 300, nullptr, 0, -1, 0, 0, 0, 0);
    sgemm<<<ge, 256>>>(emb, 300, 0, wihb, 300, 0, 1, pEW + 400, 800, 0,
                       V_, 400, 300, nullptr, 0, -1, 0, 0, 0, 0);

    // fused all-timestep LSTM: one block per SM
    const int SMEM_LSTM = (40100 + 100 * HTS + 400) * 4 + RPB * 4;
    cudaFuncSetAttribute(lstm_all, cudaFuncAttributeMaxDynamicSharedMemorySize, SMEM_LSTM);
    lstm_all<<<dim3(74, 2), 256, SMEM_LSTM>>>(rsent, body, whhf, whhb,
                                              bihf, bhhf, bihb, bhhb);

    hv_k<<<7, 1024>>>(simw);
    logits_k<<<256, 256>>>(simb);
    softpart<<<1, 1024>>>();
    attend_k<<<1600, 256>>>();

    // Q/K/V on full attend, h-batched (z=8)
    dim3 gq(4, 16, 8);
    sgemm<<<gq, 256>>>(pAtt, 200, 0, qw, 200, 40000LL, 1, pQa, 200, 409600LL,
                       S_, 200, 200, qb, 200, -1, 0, 0, 0, 0);
    sgemm<<<gq, 256>>>(pAtt, 200, 0, kw, 200, 40000LL, 1, pKa, 200, 409600LL,
                       S_, 200, 200, kb, 200, -1, 0, 0, 0, 0);
    sgemm<<<gq, 256>>>(pAtt, 200, 0, vw, 200, 40000LL, 1, pVa, 200, 409600LL,
                       S_, 200, 200, vb, 200, -1, 0, 0, 0, 0);

    for (int br = 0; br < 2; br++) {
        compact<<<2048, 192>>>(br);

        dim3 gs(32, 16, 8);
        sgemm<<<gs, 256>>>(pQc, 200, 409600LL, pKc, 200, 409600LL, 1,
                           pSC, 2048, 4194304LL, S_, S_, 200,
                           nullptr, 0, br, 1, 1, 0, (br == 0) ? 1 : 2);

        colstats<<<dim3(16, 8), 128>>>(br);
        pnorm<<<dim3(8, 2048, 8), 256>>>(br);

        dim3 go(4, 16, 8);
        sgemm<<<go, 256>>>(pSC, 2048, 4194304LL, pVc, 200, 409600LL, 0,
                           pCat, 1600, 200LL, S_, 200, S_,
                           nullptr, 0, br, 1, 0, 1, 0);

        dim3 gm(4, 16, 1);
        sgemm<<<gm, 256>>>(pCat, 1600, 0, cw, 1600, 0, 1, pMh, 200, 0,
                           S_, 200, 1600, cb, 0, br, 1, 0, 0, 0);

        featpart<<<dim3(200, 8), 256>>>(fw, br);
    }

    finalize<<<2, 256>>>(fb, out);
}

// round 11
// speedup vs baseline: 1.4101x; 1.4101x over previous
#include <cuda_runtime.h>
#include <math.h>

#define NB 2049
#define S_ 2048
#define W_ 64
#define D_ 300
#define M_ 100
#define H_ 8
#define D2_ 200
#define V_ 50000
#define RSQ 0.07071067811865475f   // 1/sqrt(200)

#define RPB 28                     // rows per LSTM block
#define RH 14                      // rows per thread-half

// ----------------------------- device scratch ------------------------------
__device__ float g_EW[V_ * 800];          // emb @ [w_ih_f | w_ih_b]^T
__device__ float g_hid[NB * D2_];         // [h_f | h_b]
__device__ float g_hv[D2_];
__device__ float g_logit[S_];
__device__ float g_prob[S_];
__device__ float g_att[S_ * D2_];
__device__ float g_Qa[H_ * S_ * D2_];
__device__ float g_Ka[H_ * S_ * D2_];
__device__ float g_Va[H_ * S_ * D2_];
__device__ float g_Qc[H_ * S_ * D2_];
__device__ float g_Kc[H_ * S_ * D2_];
__device__ float g_Vc[H_ * S_ * D2_];
__device__ float g_SC[33554432];          // 8 * 2048 * 2048 scores -> P in place
__device__ float g_mx[H_ * S_];
__device__ float g_iZ[H_ * S_];
__device__ float g_cat[S_ * H_ * D2_];    // out in cat layout [s][h*200+o]
__device__ float g_mh[S_ * D2_];
__device__ float g_fp[2 * 8 * D2_];
__device__ int   g_idx[2][S_];
__device__ int   g_n[2];

// ------------------ SGEMM: BM=128, BN=64, 8x4 microtile --------------------
// C[M,N] = A[M,K] * op(B) (+ bias[bz*sBias+n]); transB: B is (N,K) row-major.
// limBr>=0: lim=g_n[limBr]; limRows/limCols skip tiles past lim; capK caps K.
// epi: 1 -> v*RSQ ; 2 -> (1-v)*RSQ.
#define BM 128
#define BN 64
#define BK 16
#define ASTR (BM + 4)
#define BSTR (BN + 4)

__global__ void sgemm(const float* __restrict__ A, int lda, long long sA,
                      const float* __restrict__ B, int ldb, long long sB, int transB,
                      float* __restrict__ C, int ldc, long long sC,
                      int M, int N, int K,
                      const float* __restrict__ bias, int sBias,
                      int limBr, int limRows, int limCols, int capK, int epi)
{
    int bz = blockIdx.z;
    int m0 = blockIdx.y * BM;
    int n0 = blockIdx.x * BN;
    if (limBr >= 0) {
        int lim = g_n[limBr];
        if (limRows && m0 >= lim) return;
        if (limCols && n0 >= lim) return;
        if (capK) { int kc = (lim + 15) & ~15; if (kc < K) K = kc; }
    }
    A += (long long)bz * sA;
    B += (long long)bz * sB;
    C += (long long)bz * sC;

    __shared__ __align__(16) float As[BK][ASTR];
    __shared__ __align__(16) float Bs[BK][BSTR];

    int tid = threadIdx.x;            // 256 threads
    int tr = tid >> 4;                // 0..15 -> 8 rows each
    int tc = tid & 15;                // 0..15 -> 4 cols each
    float acc[8][4] = {};

    // per-thread staging coordinates
    int am = tid >> 4;                // A: rows am, am+16, ... (8 loads)
    int ak = tid & 15;
    int bn = tid >> 4;                // B(transB): rows bn, bn+16,... (4 loads)
    int bk = tid & 15;
    int bk2 = tid >> 6;               // B(noT): k = bk2, bk2+4,... (4 loads)
    int bn2 = tid & 63;

    float ra[8], rb[4];
    // prologue: load tile 0 into registers
#pragma unroll
    for (int i = 0; i < 8; i++) {
        int gm = m0 + am + i * 16, gk = ak;
        ra[i] = (gm < M && gk < K) ? A[(long long)gm * lda + gk] : 0.f;
    }
    if (transB) {
#pragma unroll
        for (int i = 0; i < 4; i++) {
            int gn = n0 + bn + i * 16, gk = bk;
            rb[i] = (gn < N && gk < K) ? B[(long long)gn * ldb + gk] : 0.f;
        }
    } else {
#pragma unroll
        for (int i = 0; i < 4; i++) {
            int gk = bk2 + i * 4, gn = n0 + bn2;
            rb[i] = (gk < K && gn < N) ? B[(long long)gk * ldb + gn] : 0.f;
        }
    }

    for (int k0 = 0; k0 < K; k0 += BK) {
        // commit current registers to smem
#pragma unroll
        for (int i = 0; i < 8; i++) As[ak][am + i * 16] = ra[i];
        if (transB) {
#pragma unroll
            for (int i = 0; i < 4; i++) Bs[bk][bn + i * 16] = rb[i];
        } else {
#pragma unroll
            for (int i = 0; i < 4; i++) Bs[bk2 + i * 4][bn2] = rb[i];
        }
        __syncthreads();

        // prefetch next tile into registers (hidden under compute)
        int kn = k0 + BK;
        if (kn < K) {
#pragma unroll
            for (int i = 0; i < 8; i++) {
                int gm = m0 + am + i * 16, gk = kn + ak;
                ra[i] = (gm < M && gk < K) ? A[(long long)gm * lda + gk] : 0.f;
            }
            if (transB) {
#pragma unroll
                for (int i = 0; i < 4; i++) {
                    int gn = n0 + bn + i * 16, gk = kn + bk;
                    rb[i] = (gn < N && gk < K) ? B[(long long)gn * ldb + gk] : 0.f;
                }
            } else {
#pragma unroll
                for (int i = 0; i < 4; i++) {
                    int gk = kn + bk2 + i * 4, gn = n0 + bn2;
                    rb[i] = (gk < K && gn < N) ? B[(long long)gk * ldb + gn] : 0.f;
                }
            }
        }

#pragma unroll
        for (int k = 0; k < BK; k++) {
            float4 a03 = *reinterpret_cast<const float4*>(&As[k][tr * 8]);
            float4 a47 = *reinterpret_cast<const float4*>(&As[k][tr * 8 + 4]);
            float4 bv  = *reinterpret_cast<const float4*>(&Bs[k][tc * 4]);
            float a[8] = {a03.x, a03.y, a03.z, a03.w, a47.x, a47.y, a47.z, a47.w};
            float b4[4] = {bv.x, bv.y, bv.z, bv.w};
#pragma unroll
            for (int i = 0; i < 8; i++) {
                acc[i][0] += a[i] * b4[0];
                acc[i][1] += a[i] * b4[1];
                acc[i][2] += a[i] * b4[2];
                acc[i][3] += a[i] * b4[3];
            }
        }
        __syncthreads();
    }
#pragma unroll
    for (int i = 0; i < 8; i++) {
        int gm = m0 + tr * 8 + i;
        if (gm >= M) continue;
#pragma unroll
        for (int j = 0; j < 4; j++) {
            int gn = n0 + tc * 4 + j;
            if (gn >= N) continue;
            float v = acc[i][j];
            if (bias) v += bias[bz * sBias + gn];
            if (epi == 1) v *= RSQ;
            else if (epi == 2) v = (1.f - v) * RSQ;
            C[(long long)gm * ldc + gn] = v;
        }
    }
}

// ------------------------- fused all-timestep LSTM --------------------------
// grid (74, 2dirs), 256 threads. Each block owns 28 rows of one direction for
// ALL 64 timesteps. c in registers. (R9-proven version.)
__global__ void lstm_all(const int* __restrict__ rsent, const int* __restrict__ body,
                         const float* __restrict__ whf, const float* __restrict__ whb,
                         const float* __restrict__ bihf, const float* __restrict__ bhhf,
                         const float* __restrict__ bihb, const float* __restrict__ bhhb)
{
    extern __shared__ float sh[];
    float* Wsh = sh;                    // [100][401]  Wsh[m*401+j] = whh[j][m]
    float* hT  = sh + 40100;            // [100][33]   hT[m*33+r]
    float* bcs = sh + 43400;            // [400]
    int*   toks = (int*)(sh + 43800);   // [28]

    int dir = blockIdx.y;
    int n0 = blockIdx.x * RPB;
    int tid = threadIdx.x;              // 256

    const float* wh = dir ? whb : whf;
    const float* bi = dir ? bihb : bihf;
    const float* bh = dir ? bhhb : bhhf;

    for (int e = tid; e < 40000; e += 256) {
        int j = e / 100, m = e - j * 100;
        Wsh[m * 401 + j] = wh[e];
    }
    for (int j = tid; j < 400; j += 256) bcs[j] = bi[j] + bh[j];
    for (int e = tid; e < 3300; e += 256) hT[e] = 0.f;
    __syncthreads();

    int m2 = tid & 127;
    int half = tid >> 7;
    int rbase = half * RH;
    bool act = (m2 < 100);

    float c[RH];
#pragma unroll
    for (int r = 0; r < RH; r++) c[r] = 0.f;

    for (int t = 0; t < 64; t++) {
        int w = dir ? (63 - t) : t;
        if (tid < RPB) {
            int n = n0 + tid;
            if (n >= NB) n = NB - 1;
            toks[tid] = (n == 0) ? rsent[w] : body[(n - 1) * W_ + w];
        }
        __syncthreads();

        float acc[4][RH];
        if (act) {
#pragma unroll
            for (int jo = 0; jo < 4; jo++) {
                int j = m2 + jo * 100;
                float bj = bcs[j];
#pragma unroll
                for (int r = 0; r < RH; r++)
                    acc[jo][r] = bj + g_EW[(long long)toks[rbase + r] * 800 + dir * 400 + j];
            }
            for (int m = 0; m < 100; m++) {
                float w0 = Wsh[m * 401 + m2];
                float w1 = Wsh[m * 401 + m2 + 100];
                float w2 = Wsh[m * 401 + m2 + 200];
                float w3 = Wsh[m * 401 + m2 + 300];
#pragma unroll
                for (int r = 0; r < RH; r++) {
                    float hv = hT[m * 33 + rbase + r];
                    acc[0][r] += w0 * hv;
                    acc[1][r] += w1 * hv;
                    acc[2][r] += w2 * hv;
                    acc[3][r] += w3 * hv;
                }
            }
        }
        __syncthreads();   // hT reads done before overwrite
        if (act) {
#pragma unroll
            for (int r = 0; r < RH; r++) {
                float fi = 1.f / (1.f + expf(-acc[0][r]));
                float ff = 1.f / (1.f + expf(-acc[1][r]));
                float gg = tanhf(acc[2][r]);
                float fo = 1.f / (1.f + expf(-acc[3][r]));
                c[r] = ff * c[r] + fi * gg;
                hT[m2 * 33 + rbase + r] = fo * tanhf(c[r]);
            }
        }
        __syncthreads();
    }

    if (act) {
#pragma unroll
        for (int r = 0; r < RH; r++) {
            int n = n0 + rbase + r;
            if (n < NB) g_hid[n * D2_ + dir * M_ + m2] = hT[m2 * 33 + rbase + r];
        }
    }
}

// ----------------------------- sim / partition -----------------------------
__global__ void hv_k(const float* __restrict__ simw)
{
    int warp = threadIdx.x >> 5, lane = threadIdx.x & 31;
    int b = blockIdx.x * 32 + warp;
    if (b >= D2_) return;
    float a = 0.f;
    for (int i = lane; i < D2_; i += 32) a += g_hid[i] * simw[i * D2_ + b];
#pragma unroll
    for (int o = 16; o; o >>= 1) a += __shfl_down_sync(0xffffffffu, a, o);
    if (lane == 0) g_hv[b] = a;
}

__global__ void logits_k(const float* __restrict__ simb)
{
    __shared__ float hv[D2_];
    int tid = threadIdx.x;
    if (tid < D2_) hv[tid] = g_hv[tid];
    __syncthreads();
    int warp = tid >> 5, lane = tid & 31;
    int s = blockIdx.x * 8 + warp;
    const float* row = g_hid + (long long)(s + 1) * D2_;
    float a = 0.f;
    for (int b = lane; b < D2_; b += 32) a += hv[b] * row[b];
#pragma unroll
    for (int o = 16; o; o >>= 1) a += __shfl_down_sync(0xffffffffu, a, o);
    if (lane == 0) g_logit[s] = a + simb[0];
}

__global__ void softpart()
{
    __shared__ float sg[S_];
    __shared__ float redm[32];
    __shared__ float reds[32];
    __shared__ int cnt[1024];
    int tid = threadIdx.x;           // 1024
    for (int s = tid; s < S_; s += 1024) {
        float l = g_logit[s];
        sg[s] = 1.f / (1.f + expf(-l));
    }
    __syncthreads();
    float m = fmaxf(sg[tid], sg[tid + 1024]);
#pragma unroll
    for (int o = 16; o; o >>= 1) m = fmaxf(m, __shfl_xor_sync(0xffffffffu, m, o));
    if ((tid & 31) == 0) redm[tid >> 5] = m;
    __syncthreads();
    if (tid < 32) {
        float v = redm[tid];
#pragma unroll
        for (int o = 16; o; o >>= 1) v = fmaxf(v, __shfl_xor_sync(0xffffffffu, v, o));
        if (tid == 0) redm[0] = v;
    }
    __syncthreads();
    float mx = redm[0];
    float z = expf(sg[tid] - mx) + expf(sg[tid + 1024] - mx);
#pragma unroll
    for (int o = 16; o; o >>= 1) z += __shfl_xor_sync(0xffffffffu, z, o);
    if ((tid & 31) == 0) reds[tid >> 5] = z;
    __syncthreads();
    if (tid < 32) {
        float v = reds[tid];
#pragma unroll
        for (int o = 16; o; o >>= 1) v += __shfl_xor_sync(0xffffffffu, v, o);
        if (tid == 0) reds[0] = v;
    }
    __syncthreads();
    float invZ = 1.f / reds[0];
    for (int s = tid; s < S_; s += 1024) g_prob[s] = expf(sg[s] - mx) * invZ;

    int a = (sg[2 * tid] >= 0.5f) ? 1 : 0;
    int b = (sg[2 * tid + 1] >= 0.5f) ? 1 : 0;
    cnt[tid] = a + b;
    __syncthreads();
    for (int off = 1; off < 1024; off <<= 1) {
        int v = cnt[tid];
        int u = (tid >= off) ? cnt[tid - off] : 0;
        __syncthreads();
        cnt[tid] = v + u;
        __syncthreads();
    }
    int pre = (tid > 0) ? cnt[tid - 1] : 0;
    int tot = cnt[1023];
    int s0 = 2 * tid, s1 = 2 * tid + 1;
    if (a) g_idx[0][pre] = s0; else g_idx[1][s0 - pre] = s0;
    int pre1 = pre + a;
    if (b) g_idx[0][pre1] = s1; else g_idx[1][s1 - pre1] = s1;
    if (tid == 0) { g_n[0] = tot; g_n[1] = S_ - tot; }
}

__global__ void attend_k()
{
    int e = blockIdx.x * 256 + threadIdx.x;
    if (e >= S_ * D2_) return;
    int s = e / D2_;
    g_att[e] = g_prob[s] * g_hid[e + D2_];
}

// -------------------------- branch-local kernels ---------------------------
__global__ void compact(int br)
{
    int p = blockIdx.x;
    if (p >= g_n[br]) return;
    int src = g_idx[br][p];
    for (int e = threadIdx.x; e < H_ * D2_; e += 192) {
        int h = e / D2_, o = e - h * D2_;
        long long di = (long long)h * (S_ * D2_) + (long long)p * D2_ + o;
        long long si = (long long)h * (S_ * D2_) + (long long)src * D2_ + o;
        g_Qc[di] = g_Qa[si];
        g_Kc[di] = g_Ka[si];
        g_Vc[di] = g_Va[si];
    }
}

__global__ void colstats(int br)
{
    int n = g_n[br];
    int t = blockIdx.x * 128 + threadIdx.x;
    if (t >= n) return;
    int h = blockIdx.y;
    const float* base = g_SC + (long long)h * S_ * S_ + t;
    float m = -1e30f;
    for (int s = 0; s < n; s++) m = fmaxf(m, base[(long long)s * S_]);
    float z = 0.f;
    for (int s = 0; s < n; s++) z += expf(base[(long long)s * S_] - m);
    g_mx[h * S_ + t] = m;
    g_iZ[h * S_ + t] = 1.f / z;
}

__global__ void pnorm(int br)
{
    int n = g_n[br];
    int s = blockIdx.y;
    if (s >= n) return;
    int capn = (n + 15) & ~15;
    int t = blockIdx.x * 256 + threadIdx.x;
    if (t >= capn) return;
    int h = blockIdx.z;
    long long ix = (long long)h * S_ * S_ + (long long)s * S_ + t;
    float v = 0.f;
    if (t < n) v = expf(g_SC[ix] - g_mx[h * S_ + t]) * g_iZ[h * S_ + t];
    g_SC[ix] = v;
}

__global__ void featpart(const float* __restrict__ fw, int br)
{
    int n = g_n[br];
    int j = blockIdx.x;
    int ch = blockIdx.y;
    int per = (n + 7) / 8;
    int s0 = ch * per;
    int s1 = s0 + per; if (s1 > n) s1 = n;
    if (s0 > n) s0 = n;
    float acc = 0.f;
    const float* base = fw + (long long)j * (S_ * D2_);
    for (long long e = (long long)s0 * D2_ + threadIdx.x; e < (long long)s1 * D2_; e += 256)
        acc += g_mh[e] * base[e];
    __shared__ float red[8];
#pragma unroll
    for (int o = 16; o; o >>= 1) acc += __shfl_xor_sync(0xffffffffu, acc, o);
    if ((threadIdx.x & 31) == 0) red[threadIdx.x >> 5] = acc;
    __syncthreads();
    if (threadIdx.x < 8) {
        float v = red[threadIdx.x];
#pragma unroll
        for (int o = 4; o; o >>= 1) v += __shfl_xor_sync(0x000000ffu, v, o);
        if (threadIdx.x == 0) g_fp[(br * 8 + ch) * D2_ + j] = v;
    }
}

__global__ void finalize(const float* __restrict__ fb, float* __restrict__ out)
{
    int i = blockIdx.x * 256 + threadIdx.x;
    if (i >= 400) return;
    int br = i / 200, j = i - br * 200;
    float a = fb[j];
    for (int c = 0; c < 8; c++) a += g_fp[(br * 8 + c) * D2_ + j];
    out[i] = a;
}

// --------------------------------- launcher --------------------------------
extern "C" void kernel_launch(void* const* d_in, const int* in_sizes, int n_in,
                              void* d_out, int out_size)
{
    const int*   rsent = (const int*)d_in[0];
    const int*   body  = (const int*)d_in[1];
    const float* emb   = (const float*)d_in[2];
    const float* wihf  = (const float*)d_in[3];
    const float* whhf  = (const float*)d_in[4];
    const float* bihf  = (const float*)d_in[5];
    const float* bhhf  = (const float*)d_in[6];
    const float* wihb  = (const float*)d_in[7];
    const float* whhb  = (const float*)d_in[8];
    const float* bihb  = (const float*)d_in[9];
    const float* bhhb  = (const float*)d_in[10];
    const float* simw  = (const float*)d_in[11];
    const float* simb  = (const float*)d_in[12];
    const float* qw    = (const float*)d_in[13];
    const float* qb    = (const float*)d_in[14];
    const float* kw    = (const float*)d_in[15];
    const float* kb    = (const float*)d_in[16];
    const float* vw    = (const float*)d_in[17];
    const float* vb    = (const float*)d_in[18];
    const float* cw    = (const float*)d_in[19];
    const float* cb    = (const float*)d_in[20];
    const float* fw    = (const float*)d_in[21];
    const float* fb    = (const float*)d_in[22];
    float* out = (float*)d_out;

    float *pEW, *pAtt, *pQa, *pKa, *pVa, *pQc, *pKc, *pVc, *pSC, *pCat, *pMh;
    cudaGetSymbolAddress((void**)&pEW, g_EW);
    cudaGetSymbolAddress((void**)&pAtt, g_att);
    cudaGetSymbolAddress((void**)&pQa, g_Qa);
    cudaGetSymbolAddress((void**)&pKa, g_Ka);
    cudaGetSymbolAddress((void**)&pVa, g_Va);
    cudaGetSymbolAddress((void**)&pQc, g_Qc);
    cudaGetSymbolAddress((void**)&pKc, g_Kc);
    cudaGetSymbolAddress((void**)&pVc, g_Vc);
    cudaGetSymbolAddress((void**)&pSC, g_SC);
    cudaGetSymbolAddress((void**)&pCat, g_cat);
    cudaGetSymbolAddress((void**)&pMh, g_mh);

    // EW = emb @ w_ih^T  (per direction)
    dim3 ge(7, 391, 1);
    sgemm<<<ge, 256>>>(emb, 300, 0, wihf, 300, 0, 1, pEW,       800, 0,
                       V_, 400, 300, nullptr, 0, -1, 0, 0, 0, 0);
    sgemm<<<ge, 256>>>(emb, 300, 0, wihb, 300, 0, 1, pEW + 400, 800, 0,
                       V_, 400, 300, nullptr, 0, -1, 0, 0, 0, 0);

    // fused all-timestep LSTM: one block per SM
    const int SMEM_LSTM = (40100 + 3300 + 400) * 4 + RPB * 4;
    cudaFuncSetAttribute(lstm_all, cudaFuncAttributeMaxDynamicSharedMemorySize, SMEM_LSTM);
    lstm_all<<<dim3(74, 2), 256, SMEM_LSTM>>>(rsent, body, whhf, whhb,
                                              bihf, bhhf, bihb, bhhb);

    hv_k<<<7, 1024>>>(simw);
    logits_k<<<256, 256>>>(simb);
    softpart<<<1, 1024>>>();
    attend_k<<<1600, 256>>>();

    // Q/K/V on full attend, h-batched (z=8)
    dim3 gq(4, 16, 8);
    sgemm<<<gq, 256>>>(pAtt, 200, 0, qw, 200, 40000LL, 1, pQa, 200, 409600LL,
                       S_, 200, 200, qb, 200, -1, 0, 0, 0, 0);
    sgemm<<<gq, 256>>>(pAtt, 200, 0, kw, 200, 40000LL, 1, pKa, 200, 409600LL,
                       S_, 200, 200, kb, 200, -1, 0, 0, 0, 0);
    sgemm<<<gq, 256>>>(pAtt, 200, 0, vw, 200, 40000LL, 1, pVa, 200, 409600LL,
                       S_, 200, 200, vb, 200, -1, 0, 0, 0, 0);

    for (int br = 0; br < 2; br++) {
        compact<<<2048, 192>>>(br);

        dim3 gs(32, 16, 8);
        sgemm<<<gs, 256>>>(pQc, 200, 409600LL, pKc, 200, 409600LL, 1,
                           pSC, 2048, 4194304LL, S_, S_, 200,
                           nullptr, 0, br, 1, 1, 0, (br == 0) ? 1 : 2);

        colstats<<<dim3(16, 8), 128>>>(br);
        pnorm<<<dim3(8, 2048, 8), 256>>>(br);

        dim3 go(4, 16, 8);
        sgemm<<<go, 256>>>(pSC, 2048, 4194304LL, pVc, 200, 409600LL, 0,
                           pCat, 1600, 200LL, S_, 200, S_,
                           nullptr, 0, br, 1, 0, 1, 0);

        dim3 gm(4, 16, 1);
        sgemm<<<gm, 256>>>(pCat, 1600, 0, cw, 1600, 0, 1, pMh, 200, 0,
                           S_, 200, 1600, cb, 0, br, 1, 0, 0, 0);

        featpart<<<dim3(200, 8), 256>>>(fw, br);
    }

    finalize<<<2, 256>>>(fb, out);
}

// round 12
// speedup vs baseline: 1.6251x; 1.1524x over previous
#include <cuda_runtime.h>
#include <math.h>

#define NB 2049
#define S_ 2048
#define W_ 64
#define D_ 300
#define M_ 100
#define H_ 8
#define D2_ 200
#define V_ 50000
#define RSQ 0.07071067811865475f   // 1/sqrt(200)

#define RPB 28                     // rows per LSTM block
#define RH 14                      // rows per thread-half

// ----------------------------- device scratch ------------------------------
__device__ float g_EW[V_ * 800];          // emb @ [w_ih_f | w_ih_b]^T
__device__ float g_hid[NB * D2_];         // [h_f | h_b]
__device__ float g_hv[D2_];
__device__ float g_logit[S_];
__device__ float g_prob[S_];
__device__ float g_att[S_ * D2_];
__device__ float g_Qa[H_ * S_ * D2_];
__device__ float g_Ka[H_ * S_ * D2_];
__device__ float g_Va[H_ * S_ * D2_];
__device__ float g_Qc[H_ * S_ * D2_];
__device__ float g_Kc[H_ * S_ * D2_];
__device__ float g_Vc[H_ * S_ * D2_];
__device__ float g_SC[33554432];          // 8 * 2048 * 2048 scores -> P in place
__device__ float g_mx[H_ * S_];
__device__ float g_iZ[H_ * S_];
__device__ float g_cat[S_ * H_ * D2_];    // out in cat layout [s][h*200+o]
__device__ float g_mh[S_ * D2_];
__device__ float g_fp[2 * 8 * D2_];
__device__ int   g_idx[2][S_];
__device__ int   g_n[2];

__device__ __forceinline__ unsigned f2tf(float v) {
    unsigned r; asm("cvt.rna.tf32.f32 %0, %1;" : "=r"(r) : "f"(v)); return r;
}

// ------------------ scalar SGEMM (fp32-exact; used for EW) -----------------
#define BM 128
#define BN 64
#define BK 16
#define ASTR 136   // stride chosen so frag/stage banks spread (8*(k)+m)
#define BSTR 72

__global__ void sgemm(const float* __restrict__ A, int lda, long long sA,
                      const float* __restrict__ B, int ldb, long long sB, int transB,
                      float* __restrict__ C, int ldc, long long sC,
                      int M, int N, int K,
                      const float* __restrict__ bias, int sBias,
                      int limBr, int limRows, int limCols, int capK, int epi)
{
    int bz = blockIdx.z;
    int m0 = blockIdx.y * BM;
    int n0 = blockIdx.x * BN;
    if (limBr >= 0) {
        int lim = g_n[limBr];
        if (limRows && m0 >= lim) return;
        if (limCols && n0 >= lim) return;
        if (capK) { int kc = (lim + 15) & ~15; if (kc < K) K = kc; }
    }
    A += (long long)bz * sA;
    B += (long long)bz * sB;
    C += (long long)bz * sC;

    __shared__ __align__(16) float As[BK][ASTR];
    __shared__ __align__(16) float Bs[BK][BSTR];

    int tid = threadIdx.x;            // 256 threads
    int tr = tid >> 4;
    int tc = tid & 15;
    float acc[8][4] = {};

    int am = tid >> 4;
    int ak = tid & 15;
    int bn = tid >> 4;
    int bk = tid & 15;
    int bk2 = tid >> 6;
    int bn2 = tid & 63;

    float ra[8], rb[4];
#pragma unroll
    for (int i = 0; i < 8; i++) {
        int gm = m0 + am + i * 16, gk = ak;
        ra[i] = (gm < M && gk < K) ? A[(long long)gm * lda + gk] : 0.f;
    }
    if (transB) {
#pragma unroll
        for (int i = 0; i < 4; i++) {
            int gn = n0 + bn + i * 16, gk = bk;
            rb[i] = (gn < N && gk < K) ? B[(long long)gn * ldb + gk] : 0.f;
        }
    } else {
#pragma unroll
        for (int i = 0; i < 4; i++) {
            int gk = bk2 + i * 4, gn = n0 + bn2;
            rb[i] = (gk < K && gn < N) ? B[(long long)gk * ldb + gn] : 0.f;
        }
    }

    for (int k0 = 0; k0 < K; k0 += BK) {
#pragma unroll
        for (int i = 0; i < 8; i++) As[ak][am + i * 16] = ra[i];
        if (transB) {
#pragma unroll
            for (int i = 0; i < 4; i++) Bs[bk][bn + i * 16] = rb[i];
        } else {
#pragma unroll
            for (int i = 0; i < 4; i++) Bs[bk2 + i * 4][bn2] = rb[i];
        }
        __syncthreads();

        int kn = k0 + BK;
        if (kn < K) {
#pragma unroll
            for (int i = 0; i < 8; i++) {
                int gm = m0 + am + i * 16, gk = kn + ak;
                ra[i] = (gm < M && gk < K) ? A[(long long)gm * lda + gk] : 0.f;
            }
            if (transB) {
#pragma unroll
                for (int i = 0; i < 4; i++) {
                    int gn = n0 + bn + i * 16, gk = kn + bk;
                    rb[i] = (gn < N && gk < K) ? B[(long long)gn * ldb + gk] : 0.f;
                }
            } else {
#pragma unroll
                for (int i = 0; i < 4; i++) {
                    int gk = kn + bk2 + i * 4, gn = n0 + bn2;
                    rb[i] = (gk < K && gn < N) ? B[(long long)gk * ldb + gn] : 0.f;
                }
            }
        }

#pragma unroll
        for (int k = 0; k < BK; k++) {
            float4 a03 = *reinterpret_cast<const float4*>(&As[k][tr * 8]);
            float4 a47 = *reinterpret_cast<const float4*>(&As[k][tr * 8 + 4]);
            float4 bv  = *reinterpret_cast<const float4*>(&Bs[k][tc * 4]);
            float a[8] = {a03.x, a03.y, a03.z, a03.w, a47.x, a47.y, a47.z, a47.w};
            float b4[4] = {bv.x, bv.y, bv.z, bv.w};
#pragma unroll
            for (int i = 0; i < 8; i++) {
                acc[i][0] += a[i] * b4[0];
                acc[i][1] += a[i] * b4[1];
                acc[i][2] += a[i] * b4[2];
                acc[i][3] += a[i] * b4[3];
            }
        }
        __syncthreads();
    }
#pragma unroll
    for (int i = 0; i < 8; i++) {
        int gm = m0 + tr * 8 + i;
        if (gm >= M) continue;
#pragma unroll
        for (int j = 0; j < 4; j++) {
            int gn = n0 + tc * 4 + j;
            if (gn >= N) continue;
            float v = acc[i][j];
            if (bias) v += bias[bz * sBias + gn];
            if (epi == 1) v *= RSQ;
            else if (epi == 2) v = (1.f - v) * RSQ;
            C[(long long)gm * ldc + gn] = v;
        }
    }
}

// ----------------- TF32 tensor GEMM (post-mask paths only) -----------------
// Same interface/semantics as sgemm; operands rounded to tf32.
__global__ void tgemm(const float* __restrict__ A, int lda, long long sA,
                      const float* __restrict__ B, int ldb, long long sB, int transB,
                      float* __restrict__ C, int ldc, long long sC,
                      int M, int N, int K,
                      const float* __restrict__ bias, int sBias,
                      int limBr, int limRows, int limCols, int capK, int epi)
{
    int bz = blockIdx.z;
    int m0 = blockIdx.y * BM;
    int n0 = blockIdx.x * BN;
    if (limBr >= 0) {
        int lim = g_n[limBr];
        if (limRows && m0 >= lim) return;
        if (limCols && n0 >= lim) return;
        if (capK) { int kc = (lim + 15) & ~15; if (kc < K) K = kc; }
    }
    A += (long long)bz * sA;
    B += (long long)bz * sB;
    C += (long long)bz * sC;

    __shared__ __align__(16) float As[BK][ASTR];
    __shared__ __align__(16) float Bs[BK][BSTR];

    int tid = threadIdx.x;            // 256 threads = 8 warps (4m x 2n)
    int lane = tid & 31;
    int wrp = tid >> 5;
    int wm = (wrp & 3) * 32;
    int wn = (wrp >> 2) * 32;
    int grp = lane >> 2;              // 0..7
    int four = lane & 3;              // 0..3

    float acc[2][4][4];
#pragma unroll
    for (int i = 0; i < 2; i++)
#pragma unroll
        for (int j = 0; j < 4; j++)
#pragma unroll
            for (int q = 0; q < 4; q++) acc[i][j][q] = 0.f;

    int am = tid >> 4;
    int ak = tid & 15;
    int bn = tid >> 4;
    int bk = tid & 15;
    int bk2 = tid >> 6;
    int bn2 = tid & 63;

    float ra[8], rb[4];
#pragma unroll
    for (int i = 0; i < 8; i++) {
        int gm = m0 + am + i * 16, gk = ak;
        ra[i] = (gm < M && gk < K) ? A[(long long)gm * lda + gk] : 0.f;
    }
    if (transB) {
#pragma unroll
        for (int i = 0; i < 4; i++) {
            int gn = n0 + bn + i * 16, gk = bk;
            rb[i] = (gn < N && gk < K) ? B[(long long)gn * ldb + gk] : 0.f;
        }
    } else {
#pragma unroll
        for (int i = 0; i < 4; i++) {
            int gk = bk2 + i * 4, gn = n0 + bn2;
            rb[i] = (gk < K && gn < N) ? B[(long long)gk * ldb + gn] : 0.f;
        }
    }

    for (int k0 = 0; k0 < K; k0 += BK) {
        // commit (tf32-rounded) to smem
#pragma unroll
        for (int i = 0; i < 8; i++) As[ak][am + i * 16] = __uint_as_float(f2tf(ra[i]));
        if (transB) {
#pragma unroll
            for (int i = 0; i < 4; i++) Bs[bk][bn + i * 16] = __uint_as_float(f2tf(rb[i]));
        } else {
#pragma unroll
            for (int i = 0; i < 4; i++) Bs[bk2 + i * 4][bn2] = __uint_as_float(f2tf(rb[i]));
        }
        __syncthreads();

        int kn = k0 + BK;
        if (kn < K) {
#pragma unroll
            for (int i = 0; i < 8; i++) {
                int gm = m0 + am + i * 16, gk = kn + ak;
                ra[i] = (gm < M && gk < K) ? A[(long long)gm * lda + gk] : 0.f;
            }
            if (transB) {
#pragma unroll
                for (int i = 0; i < 4; i++) {
                    int gn = n0 + bn + i * 16, gk = kn + bk;
                    rb[i] = (gn < N && gk < K) ? B[(long long)gn * ldb + gk] : 0.f;
                }
            } else {
#pragma unroll
                for (int i = 0; i < 4; i++) {
                    int gk = kn + bk2 + i * 4, gn = n0 + bn2;
                    rb[i] = (gk < K && gn < N) ? B[(long long)gk * ldb + gn] : 0.f;
                }
            }
        }

#pragma unroll
        for (int kk = 0; kk < BK; kk += 8) {
            unsigned a[2][4];
#pragma unroll
            for (int ma = 0; ma < 2; ma++) {
                int mb = wm + ma * 16 + grp;
                a[ma][0] = __float_as_uint(As[kk + four][mb]);
                a[ma][1] = __float_as_uint(As[kk + four][mb + 8]);
                a[ma][2] = __float_as_uint(As[kk + 4 + four][mb]);
                a[ma][3] = __float_as_uint(As[kk + 4 + four][mb + 8]);
            }
#pragma unroll
            for (int na = 0; na < 4; na++) {
                int nb = wn + na * 8 + grp;
                unsigned b0 = __float_as_uint(Bs[kk + four][nb]);
                unsigned b1 = __float_as_uint(Bs[kk + 4 + four][nb]);
#pragma unroll
                for (int ma = 0; ma < 2; ma++) {
                    asm("mma.sync.aligned.m16n8k8.row.col.f32.tf32.tf32.f32 "
                        "{%0,%1,%2,%3}, {%4,%5,%6,%7}, {%8,%9}, {%0,%1,%2,%3};"
                        : "+f"(acc[ma][na][0]), "+f"(acc[ma][na][1]),
                          "+f"(acc[ma][na][2]), "+f"(acc[ma][na][3])
                        : "r"(a[ma][0]), "r"(a[ma][1]), "r"(a[ma][2]), "r"(a[ma][3]),
                          "r"(b0), "r"(b1));
                }
            }
        }
        __syncthreads();
    }

    // epilogue: c0 (r, c), c1 (r, c+1), c2 (r+8, c), c3 (r+8, c+1)
#pragma unroll
    for (int ma = 0; ma < 2; ma++) {
#pragma unroll
        for (int na = 0; na < 4; na++) {
            int gmb = m0 + wm + ma * 16 + grp;
            int gnb = n0 + wn + na * 8 + 2 * four;
#pragma unroll
            for (int q = 0; q < 4; q++) {
                int gm = gmb + (q >> 1) * 8;
                int gn = gnb + (q & 1);
                if (gm >= M || gn >= N) continue;
                float v = acc[ma][na][q];
                if (bias) v += bias[bz * sBias + gn];
                if (epi == 1) v *= RSQ;
                else if (epi == 2) v = (1.f - v) * RSQ;
                C[(long long)gm * ldc + gn] = v;
            }
        }
    }
}

// ------------------------- fused all-timestep LSTM --------------------------
__global__ void lstm_all(const int* __restrict__ rsent, const int* __restrict__ body,
                         const float* __restrict__ whf, const float* __restrict__ whb,
                         const float* __restrict__ bihf, const float* __restrict__ bhhf,
                         const float* __restrict__ bihb, const float* __restrict__ bhhb)
{
    extern __shared__ float sh[];
    float* Wsh = sh;                    // [100][401]
    float* hT  = sh + 40100;            // [100][33]
    float* bcs = sh + 43400;            // [400]
    int*   toks = (int*)(sh + 43800);   // [28]

    int dir = blockIdx.y;
    int n0 = blockIdx.x * RPB;
    int tid = threadIdx.x;

    const float* wh = dir ? whb : whf;
    const float* bi = dir ? bihb : bihf;
    const float* bh = dir ? bhhb : bhhf;

    for (int e = tid; e < 40000; e += 256) {
        int j = e / 100, m = e - j * 100;
        Wsh[m * 401 + j] = wh[e];
    }
    for (int j = tid; j < 400; j += 256) bcs[j] = bi[j] + bh[j];
    for (int e = tid; e < 3300; e += 256) hT[e] = 0.f;
    __syncthreads();

    int m2 = tid & 127;
    int half = tid >> 7;
    int rbase = half * RH;
    bool act = (m2 < 100);

    float c[RH];
#pragma unroll
    for (int r = 0; r < RH; r++) c[r] = 0.f;

    for (int t = 0; t < 64; t++) {
        int w = dir ? (63 - t) : t;
        if (tid < RPB) {
            int n = n0 + tid;
            if (n >= NB) n = NB - 1;
            toks[tid] = (n == 0) ? rsent[w] : body[(n - 1) * W_ + w];
        }
        __syncthreads();

        float acc[4][RH];
        if (act) {
#pragma unroll
            for (int jo = 0; jo < 4; jo++) {
                int j = m2 + jo * 100;
                float bj = bcs[j];
#pragma unroll
                for (int r = 0; r < RH; r++)
                    acc[jo][r] = bj + g_EW[(long long)toks[rbase + r] * 800 + dir * 400 + j];
            }
            for (int m = 0; m < 100; m++) {
                float w0 = Wsh[m * 401 + m2];
                float w1 = Wsh[m * 401 + m2 + 100];
                float w2 = Wsh[m * 401 + m2 + 200];
                float w3 = Wsh[m * 401 + m2 + 300];
#pragma unroll
                for (int r = 0; r < RH; r++) {
                    float hv = hT[m * 33 + rbase + r];
                    acc[0][r] += w0 * hv;
                    acc[1][r] += w1 * hv;
                    acc[2][r] += w2 * hv;
                    acc[3][r] += w3 * hv;
                }
            }
        }
        __syncthreads();
        if (act) {
#pragma unroll
            for (int r = 0; r < RH; r++) {
                float fi = 1.f / (1.f + expf(-acc[0][r]));
                float ff = 1.f / (1.f + expf(-acc[1][r]));
                float gg = tanhf(acc[2][r]);
                float fo = 1.f / (1.f + expf(-acc[3][r]));
                c[r] = ff * c[r] + fi * gg;
                hT[m2 * 33 + rbase + r] = fo * tanhf(c[r]);
            }
        }
        __syncthreads();
    }

    if (act) {
#pragma unroll
        for (int r = 0; r < RH; r++) {
            int n = n0 + rbase + r;
            if (n < NB) g_hid[n * D2_ + dir * M_ + m2] = hT[m2 * 33 + rbase + r];
        }
    }
}

// ----------------------------- sim / partition -----------------------------
__global__ void hv_k(const float* __restrict__ simw)
{
    int warp = threadIdx.x >> 5, lane = threadIdx.x & 31;
    int b = blockIdx.x * 32 + warp;
    if (b >= D2_) return;
    float a = 0.f;
    for (int i = lane; i < D2_; i += 32) a += g_hid[i] * simw[i * D2_ + b];
#pragma unroll
    for (int o = 16; o; o >>= 1) a += __shfl_down_sync(0xffffffffu, a, o);
    if (lane == 0) g_hv[b] = a;
}

__global__ void logits_k(const float* __restrict__ simb)
{
    __shared__ float hv[D2_];
    int tid = threadIdx.x;
    if (tid < D2_) hv[tid] = g_hv[tid];
    __syncthreads();
    int warp = tid >> 5, lane = tid & 31;
    int s = blockIdx.x * 8 + warp;
    const float* row = g_hid + (long long)(s + 1) * D2_;
    float a = 0.f;
    for (int b = lane; b < D2_; b += 32) a += hv[b] * row[b];
#pragma unroll
    for (int o = 16; o; o >>= 1) a += __shfl_down_sync(0xffffffffu, a, o);
    if (lane == 0) g_logit[s] = a + simb[0];
}

__global__ void softpart()
{
    __shared__ float sg[S_];
    __shared__ float redm[32];
    __shared__ float reds[32];
    __shared__ int cnt[1024];
    int tid = threadIdx.x;           // 1024
    for (int s = tid; s < S_; s += 1024) {
        float l = g_logit[s];
        sg[s] = 1.f / (1.f + expf(-l));
    }
    __syncthreads();
    float m = fmaxf(sg[tid], sg[tid + 1024]);
#pragma unroll
    for (int o = 16; o; o >>= 1) m = fmaxf(m, __shfl_xor_sync(0xffffffffu, m, o));
    if ((tid & 31) == 0) redm[tid >> 5] = m;
    __syncthreads();
    if (tid < 32) {
        float v = redm[tid];
#pragma unroll
        for (int o = 16; o; o >>= 1) v = fmaxf(v, __shfl_xor_sync(0xffffffffu, v, o));
        if (tid == 0) redm[0] = v;
    }
    __syncthreads();
    float mx = redm[0];
    float z = expf(sg[tid] - mx) + expf(sg[tid + 1024] - mx);
#pragma unroll
    for (int o = 16; o; o >>= 1) z += __shfl_xor_sync(0xffffffffu, z, o);
    if ((tid & 31) == 0) reds[tid >> 5] = z;
    __syncthreads();
    if (tid < 32) {
        float v = reds[tid];
#pragma unroll
        for (int o = 16; o; o >>= 1) v += __shfl_xor_sync(0xffffffffu, v, o);
        if (tid == 0) reds[0] = v;
    }
    __syncthreads();
    float invZ = 1.f / reds[0];
    for (int s = tid; s < S_; s += 1024) g_prob[s] = expf(sg[s] - mx) * invZ;

    int a = (sg[2 * tid] >= 0.5f) ? 1 : 0;
    int b = (sg[2 * tid + 1] >= 0.5f) ? 1 : 0;
    cnt[tid] = a + b;
    __syncthreads();
    for (int off = 1; off < 1024; off <<= 1) {
        int v = cnt[tid];
        int u = (tid >= off) ? cnt[tid - off] : 0;
        __syncthreads();
        cnt[tid] = v + u;
        __syncthreads();
    }
    int pre = (tid > 0) ? cnt[tid - 1] : 0;
    int tot = cnt[1023];
    int s0 = 2 * tid, s1 = 2 * tid + 1;
    if (a) g_idx[0][pre] = s0; else g_idx[1][s0 - pre] = s0;
    int pre1 = pre + a;
    if (b) g_idx[0][pre1] = s1; else g_idx[1][s1 - pre1] = s1;
    if (tid == 0) { g_n[0] = tot; g_n[1] = S_ - tot; }
}

__global__ void attend_k()
{
    int e = blockIdx.x * 256 + threadIdx.x;
    if (e >= S_ * D2_) return;
    int s = e / D2_;
    g_att[e] = g_prob[s] * g_hid[e + D2_];
}

// -------------------------- branch-local kernels ---------------------------
__global__ void compact(int br)
{
    int p = blockIdx.x;
    if (p >= g_n[br]) return;
    int src = g_idx[br][p];
    for (int e = threadIdx.x; e < H_ * D2_; e += 192) {
        int h = e / D2_, o = e - h * D2_;
        long long di = (long long)h * (S_ * D2_) + (long long)p * D2_ + o;
        long long si = (long long)h * (S_ * D2_) + (long long)src * D2_ + o;
        g_Qc[di] = g_Qa[si];
        g_Kc[di] = g_Ka[si];
        g_Vc[di] = g_Va[si];
    }
}

__global__ void colstats(int br)
{
    int n = g_n[br];
    int t = blockIdx.x * 128 + threadIdx.x;
    if (t >= n) return;
    int h = blockIdx.y;
    const float* base = g_SC + (long long)h * S_ * S_ + t;
    float m = -1e30f;
    for (int s = 0; s < n; s++) m = fmaxf(m, base[(long long)s * S_]);
    float z = 0.f;
    for (int s = 0; s < n; s++) z += expf(base[(long long)s * S_] - m);
    g_mx[h * S_ + t] = m;
    g_iZ[h * S_ + t] = 1.f / z;
}

__global__ void pnorm(int br)
{
    int n = g_n[br];
    int s = blockIdx.y;
    if (s >= n) return;
    int capn = (n + 15) & ~15;
    int t = blockIdx.x * 256 + threadIdx.x;
    if (t >= capn) return;
    int h = blockIdx.z;
    long long ix = (long long)h * S_ * S_ + (long long)s * S_ + t;
    float v = 0.f;
    if (t < n) v = expf(g_SC[ix] - g_mx[h * S_ + t]) * g_iZ[h * S_ + t];
    g_SC[ix] = v;
}

__global__ void featpart(const float* __restrict__ fw, int br)
{
    int n = g_n[br];
    int j = blockIdx.x;
    int ch = blockIdx.y;
    int per = (n + 7) / 8;
    int s0 = ch * per;
    int s1 = s0 + per; if (s1 > n) s1 = n;
    if (s0 > n) s0 = n;
    float acc = 0.f;
    const float* base = fw + (long long)j * (S_ * D2_);
    for (long long e = (long long)s0 * D2_ + threadIdx.x; e < (long long)s1 * D2_; e += 256)
        acc += g_mh[e] * base[e];
    __shared__ float red[8];
#pragma unroll
    for (int o = 16; o; o >>= 1) acc += __shfl_xor_sync(0xffffffffu, acc, o);
    if ((threadIdx.x & 31) == 0) red[threadIdx.x >> 5] = acc;
    __syncthreads();
    if (threadIdx.x < 8) {
        float v = red[threadIdx.x];
#pragma unroll
        for (int o = 4; o; o >>= 1) v += __shfl_xor_sync(0x000000ffu, v, o);
        if (threadIdx.x == 0) g_fp[(br * 8 + ch) * D2_ + j] = v;
    }
}

__global__ void finalize(const float* __restrict__ fb, float* __restrict__ out)
{
    int i = blockIdx.x * 256 + threadIdx.x;
    if (i >= 400) return;
    int br = i / 200, j = i - br * 200;
    float a = fb[j];
    for (int c = 0; c < 8; c++) a += g_fp[(br * 8 + c) * D2_ + j];
    out[i] = a;
}

// --------------------------------- launcher --------------------------------
extern "C" void kernel_launch(void* const* d_in, const int* in_sizes, int n_in,
                              void* d_out, int out_size)
{
    const int*   rsent = (const int*)d_in[0];
    const int*   body  = (const int*)d_in[1];
    const float* emb   = (const float*)d_in[2];
    const float* wihf  = (const float*)d_in[3];
    const float* whhf  = (const float*)d_in[4];
    const float* bihf  = (const float*)d_in[5];
    const float* bhhf  = (const float*)d_in[6];
    const float* wihb  = (const float*)d_in[7];
    const float* whhb  = (const float*)d_in[8];
    const float* bihb  = (const float*)d_in[9];
    const float* bhhb  = (const float*)d_in[10];
    const float* simw  = (const float*)d_in[11];
    const float* simb  = (const float*)d_in[12];
    const float* qw    = (const float*)d_in[13];
    const float* qb    = (const float*)d_in[14];
    const float* kw    = (const float*)d_in[15];
    const float* kb    = (const float*)d_in[16];
    const float* vw    = (const float*)d_in[17];
    const float* vb    = (const float*)d_in[18];
    const float* cw    = (const float*)d_in[19];
    const float* cb    = (const float*)d_in[20];
    const float* fw    = (const float*)d_in[21];
    const float* fb    = (const float*)d_in[22];
    float* out = (float*)d_out;

    float *pEW, *pAtt, *pQa, *pKa, *pVa, *pQc, *pKc, *pVc, *pSC, *pCat, *pMh;
    cudaGetSymbolAddress((void**)&pEW, g_EW);
    cudaGetSymbolAddress((void**)&pAtt, g_att);
    cudaGetSymbolAddress((void**)&pQa, g_Qa);
    cudaGetSymbolAddress((void**)&pKa, g_Ka);
    cudaGetSymbolAddress((void**)&pVa, g_Va);
    cudaGetSymbolAddress((void**)&pQc, g_Qc);
    cudaGetSymbolAddress((void**)&pKc, g_Kc);
    cudaGetSymbolAddress((void**)&pVc, g_Vc);
    cudaGetSymbolAddress((void**)&pSC, g_SC);
    cudaGetSymbolAddress((void**)&pCat, g_cat);
    cudaGetSymbolAddress((void**)&pMh, g_mh);

    // EW = emb @ w_ih^T  (fp32-exact; feeds the mask path)
    dim3 ge(7, 391, 1);
    sgemm<<<ge, 256>>>(emb, 300, 0, wihf, 300, 0, 1, pEW,       800, 0,
                       V_, 400, 300, nullptr, 0, -1, 0, 0, 0, 0);
    sgemm<<<ge, 256>>>(emb, 300, 0, wihb, 300, 0, 1, pEW + 400, 800, 0,
                       V_, 400, 300, nullptr, 0, -1, 0, 0, 0, 0);

    const int SMEM_LSTM = (40100 + 3300 + 400) * 4 + RPB * 4;
    cudaFuncSetAttribute(lstm_all, cudaFuncAttributeMaxDynamicSharedMemorySize, SMEM_LSTM);
    lstm_all<<<dim3(74, 2), 256, SMEM_LSTM>>>(rsent, body, whhf, whhb,
                                              bihf, bhhf, bihb, bhhb);

    hv_k<<<7, 1024>>>(simw);
    logits_k<<<256, 256>>>(simb);
    softpart<<<1, 1024>>>();
    attend_k<<<1600, 256>>>();

    // Q/K/V on full attend, h-batched (z=8) — TF32 tensor path
    dim3 gq(4, 16, 8);
    tgemm<<<gq, 256>>>(pAtt, 200, 0, qw, 200, 40000LL, 1, pQa, 200, 409600LL,
                       S_, 200, 200, qb, 200, -1, 0, 0, 0, 0);
    tgemm<<<gq, 256>>>(pAtt, 200, 0, kw, 200, 40000LL, 1, pKa, 200, 409600LL,
                       S_, 200, 200, kb, 200, -1, 0, 0, 0, 0);
    tgemm<<<gq, 256>>>(pAtt, 200, 0, vw, 200, 40000LL, 1, pVa, 200, 409600LL,
                       S_, 200, 200, vb, 200, -1, 0, 0, 0, 0);

    for (int br = 0; br < 2; br++) {
        compact<<<2048, 192>>>(br);

        dim3 gs(32, 16, 8);
        tgemm<<<gs, 256>>>(pQc, 200, 409600LL, pKc, 200, 409600LL, 1,
                           pSC, 2048, 4194304LL, S_, S_, 200,
                           nullptr, 0, br, 1, 1, 0, (br == 0) ? 1 : 2);

        colstats<<<dim3(16, 8), 128>>>(br);
        pnorm<<<dim3(8, 2048, 8), 256>>>(br);

        dim3 go(4, 16, 8);
        tgemm<<<go, 256>>>(pSC, 2048, 4194304LL, pVc, 200, 409600LL, 0,
                           pCat, 1600, 200LL, S_, 200, S_,
                           nullptr, 0, br, 1, 0, 1, 0);

        dim3 gm(4, 16, 1);
        tgemm<<<gm, 256>>>(pCat, 1600, 0, cw, 1600, 0, 1, pMh, 200, 0,
                           S_, 200, 1600, cb, 0, br, 1, 0, 0, 0);

        featpart<<<dim3(200, 8), 256>>>(fw, br);
    }

    finalize<<<2, 256>>>(fb, out);
}

// round 13
// speedup vs baseline: 1.8727x; 1.1524x over previous
#include <cuda_runtime.h>
#include <math.h>

#define NB 2049
#define S_ 2048
#define W_ 64
#define D_ 300
#define M_ 100
#define H_ 8
#define D2_ 200
#define V_ 50000
#define RSQ 0.07071067811865475f   // 1/sqrt(200)

#define RPB 28                     // rows per LSTM block
#define RH 14                      // rows per thread-half

// ----------------------------- device scratch ------------------------------
__device__ float g_EW[V_ * 800];          // emb @ [w_ih_f | w_ih_b]^T
__device__ float g_hid[NB * D2_];         // [h_f | h_b]
__device__ float g_hv[D2_];
__device__ float g_logit[S_];
__device__ float g_prob[S_];
__device__ float g_att[S_ * D2_];
__device__ float g_Qa[H_ * S_ * D2_];
__device__ float g_Ka[H_ * S_ * D2_];
__device__ float g_Va[H_ * S_ * D2_];
__device__ float g_Qc[H_ * S_ * D2_];
__device__ float g_Kc[H_ * S_ * D2_];
__device__ float g_Vc[H_ * S_ * D2_];
__device__ float g_SC[33554432];          // 8 * 2048 * 2048 scores -> P in place
__device__ float g_mx[H_ * S_];
__device__ float g_iZ[H_ * S_];
__device__ float g_cat[S_ * H_ * D2_];    // out in cat layout [s][h*200+o]
__device__ float g_mh[S_ * D2_];
__device__ float g_fp[2 * 8 * D2_];
__device__ int   g_idx[2][S_];
__device__ int   g_n[2];

__device__ __forceinline__ unsigned f2tf(float v) {
    unsigned r; asm("cvt.rna.tf32.f32 %0, %1;" : "=r"(r) : "f"(v)); return r;
}

// ------------------------- scalar SGEMM (fp32-exact) -----------------------
#define BM 128
#define BN 64
#define BK 16
#define ASTR 136
#define BSTR 72

__global__ void sgemm(const float* __restrict__ A, int lda, long long sA,
                      const float* __restrict__ B, int ldb, long long sB, int transB,
                      float* __restrict__ C, int ldc, long long sC,
                      int M, int N, int K,
                      const float* __restrict__ bias, int sBias,
                      int limBr, int limRows, int limCols, int capK, int epi)
{
    int bz = blockIdx.z;
    int m0 = blockIdx.y * BM;
    int n0 = blockIdx.x * BN;
    if (limBr >= 0) {
        int lim = g_n[limBr];
        if (limRows && m0 >= lim) return;
        if (limCols && n0 >= lim) return;
        if (capK) { int kc = (lim + 15) & ~15; if (kc < K) K = kc; }
    }
    A += (long long)bz * sA;
    B += (long long)bz * sB;
    C += (long long)bz * sC;

    __shared__ __align__(16) float As[BK][ASTR];
    __shared__ __align__(16) float Bs[BK][BSTR];

    int tid = threadIdx.x;
    int tr = tid >> 4;
    int tc = tid & 15;
    float acc[8][4] = {};

    int am = tid >> 4;
    int ak = tid & 15;
    int bn = tid >> 4;
    int bk = tid & 15;
    int bk2 = tid >> 6;
    int bn2 = tid & 63;

    float ra[8], rb[4];
#pragma unroll
    for (int i = 0; i < 8; i++) {
        int gm = m0 + am + i * 16, gk = ak;
        ra[i] = (gm < M && gk < K) ? A[(long long)gm * lda + gk] : 0.f;
    }
    if (transB) {
#pragma unroll
        for (int i = 0; i < 4; i++) {
            int gn = n0 + bn + i * 16, gk = bk;
            rb[i] = (gn < N && gk < K) ? B[(long long)gn * ldb + gk] : 0.f;
        }
    } else {
#pragma unroll
        for (int i = 0; i < 4; i++) {
            int gk = bk2 + i * 4, gn = n0 + bn2;
            rb[i] = (gk < K && gn < N) ? B[(long long)gk * ldb + gn] : 0.f;
        }
    }

    for (int k0 = 0; k0 < K; k0 += BK) {
#pragma unroll
        for (int i = 0; i < 8; i++) As[ak][am + i * 16] = ra[i];
        if (transB) {
#pragma unroll
            for (int i = 0; i < 4; i++) Bs[bk][bn + i * 16] = rb[i];
        } else {
#pragma unroll
            for (int i = 0; i < 4; i++) Bs[bk2 + i * 4][bn2] = rb[i];
        }
        __syncthreads();

        int kn = k0 + BK;
        if (kn < K) {
#pragma unroll
            for (int i = 0; i < 8; i++) {
                int gm = m0 + am + i * 16, gk = kn + ak;
                ra[i] = (gm < M && gk < K) ? A[(long long)gm * lda + gk] : 0.f;
            }
            if (transB) {
#pragma unroll
                for (int i = 0; i < 4; i++) {
                    int gn = n0 + bn + i * 16, gk = kn + bk;
                    rb[i] = (gn < N && gk < K) ? B[(long long)gn * ldb + gk] : 0.f;
                }
            } else {
#pragma unroll
                for (int i = 0; i < 4; i++) {
                    int gk = kn + bk2 + i * 4, gn = n0 + bn2;
                    rb[i] = (gk < K && gn < N) ? B[(long long)gk * ldb + gn] : 0.f;
                }
            }
        }

#pragma unroll
        for (int k = 0; k < BK; k++) {
            float4 a03 = *reinterpret_cast<const float4*>(&As[k][tr * 8]);
            float4 a47 = *reinterpret_cast<const float4*>(&As[k][tr * 8 + 4]);
            float4 bv  = *reinterpret_cast<const float4*>(&Bs[k][tc * 4]);
            float a[8] = {a03.x, a03.y, a03.z, a03.w, a47.x, a47.y, a47.z, a47.w};
            float b4[4] = {bv.x, bv.y, bv.z, bv.w};
#pragma unroll
            for (int i = 0; i < 8; i++) {
                acc[i][0] += a[i] * b4[0];
                acc[i][1] += a[i] * b4[1];
                acc[i][2] += a[i] * b4[2];
                acc[i][3] += a[i] * b4[3];
            }
        }
        __syncthreads();
    }
#pragma unroll
    for (int i = 0; i < 8; i++) {
        int gm = m0 + tr * 8 + i;
        if (gm >= M) continue;
#pragma unroll
        for (int j = 0; j < 4; j++) {
            int gn = n0 + tc * 4 + j;
            if (gn >= N) continue;
            float v = acc[i][j];
            if (bias) v += bias[bz * sBias + gn];
            if (epi == 1) v *= RSQ;
            else if (epi == 2) v = (1.f - v) * RSQ;
            C[(long long)gm * ldc + gn] = v;
        }
    }
}

// --------------------------- TF32 tensor GEMM ------------------------------
__global__ void tgemm(const float* __restrict__ A, int lda, long long sA,
                      const float* __restrict__ B, int ldb, long long sB, int transB,
                      float* __restrict__ C, int ldc, long long sC,
                      int M, int N, int K,
                      const float* __restrict__ bias, int sBias,
                      int limBr, int limRows, int limCols, int capK, int epi)
{
    int bz = blockIdx.z;
    int m0 = blockIdx.y * BM;
    int n0 = blockIdx.x * BN;
    if (limBr >= 0) {
        int lim = g_n[limBr];
        if (limRows && m0 >= lim) return;
        if (limCols && n0 >= lim) return;
        if (capK) { int kc = (lim + 15) & ~15; if (kc < K) K = kc; }
    }
    A += (long long)bz * sA;
    B += (long long)bz * sB;
    C += (long long)bz * sC;

    __shared__ __align__(16) float As[BK][ASTR];
    __shared__ __align__(16) float Bs[BK][BSTR];

    int tid = threadIdx.x;            // 256 threads = 8 warps (4m x 2n)
    int lane = tid & 31;
    int wrp = tid >> 5;
    int wm = (wrp & 3) * 32;
    int wn = (wrp >> 2) * 32;
    int grp = lane >> 2;
    int four = lane & 3;

    float acc[2][4][4];
#pragma unroll
    for (int i = 0; i < 2; i++)
#pragma unroll
        for (int j = 0; j < 4; j++)
#pragma unroll
            for (int q = 0; q < 4; q++) acc[i][j][q] = 0.f;

    int am = tid >> 4;
    int ak = tid & 15;
    int bn = tid >> 4;
    int bk = tid & 15;
    int bk2 = tid >> 6;
    int bn2 = tid & 63;

    float ra[8], rb[4];
#pragma unroll
    for (int i = 0; i < 8; i++) {
        int gm = m0 + am + i * 16, gk = ak;
        ra[i] = (gm < M && gk < K) ? A[(long long)gm * lda + gk] : 0.f;
    }
    if (transB) {
#pragma unroll
        for (int i = 0; i < 4; i++) {
            int gn = n0 + bn + i * 16, gk = bk;
            rb[i] = (gn < N && gk < K) ? B[(long long)gn * ldb + gk] : 0.f;
        }
    } else {
#pragma unroll
        for (int i = 0; i < 4; i++) {
            int gk = bk2 + i * 4, gn = n0 + bn2;
            rb[i] = (gk < K && gn < N) ? B[(long long)gk * ldb + gn] : 0.f;
        }
    }

    for (int k0 = 0; k0 < K; k0 += BK) {
#pragma unroll
        for (int i = 0; i < 8; i++) As[ak][am + i * 16] = __uint_as_float(f2tf(ra[i]));
        if (transB) {
#pragma unroll
            for (int i = 0; i < 4; i++) Bs[bk][bn + i * 16] = __uint_as_float(f2tf(rb[i]));
        } else {
#pragma unroll
            for (int i = 0; i < 4; i++) Bs[bk2 + i * 4][bn2] = __uint_as_float(f2tf(rb[i]));
        }
        __syncthreads();

        int kn = k0 + BK;
        if (kn < K) {
#pragma unroll
            for (int i = 0; i < 8; i++) {
                int gm = m0 + am + i * 16, gk = kn + ak;
                ra[i] = (gm < M && gk < K) ? A[(long long)gm * lda + gk] : 0.f;
            }
            if (transB) {
#pragma unroll
                for (int i = 0; i < 4; i++) {
                    int gn = n0 + bn + i * 16, gk = kn + bk;
                    rb[i] = (gn < N && gk < K) ? B[(long long)gn * ldb + gk] : 0.f;
                }
            } else {
#pragma unroll
                for (int i = 0; i < 4; i++) {
                    int gk = kn + bk2 + i * 4, gn = n0 + bn2;
                    rb[i] = (gk < K && gn < N) ? B[(long long)gk * ldb + gn] : 0.f;
                }
            }
        }

#pragma unroll
        for (int kk = 0; kk < BK; kk += 8) {
            unsigned a[2][4];
#pragma unroll
            for (int ma = 0; ma < 2; ma++) {
                int mb = wm + ma * 16 + grp;
                a[ma][0] = __float_as_uint(As[kk + four][mb]);
                a[ma][1] = __float_as_uint(As[kk + four][mb + 8]);
                a[ma][2] = __float_as_uint(As[kk + 4 + four][mb]);
                a[ma][3] = __float_as_uint(As[kk + 4 + four][mb + 8]);
            }
#pragma unroll
            for (int na = 0; na < 4; na++) {
                int nb = wn + na * 8 + grp;
                unsigned b0 = __float_as_uint(Bs[kk + four][nb]);
                unsigned b1 = __float_as_uint(Bs[kk + 4 + four][nb]);
#pragma unroll
                for (int ma = 0; ma < 2; ma++) {
                    asm("mma.sync.aligned.m16n8k8.row.col.f32.tf32.tf32.f32 "
                        "{%0,%1,%2,%3}, {%4,%5,%6,%7}, {%8,%9}, {%0,%1,%2,%3};"
                        : "+f"(acc[ma][na][0]), "+f"(acc[ma][na][1]),
                          "+f"(acc[ma][na][2]), "+f"(acc[ma][na][3])
                        : "r"(a[ma][0]), "r"(a[ma][1]), "r"(a[ma][2]), "r"(a[ma][3]),
                          "r"(b0), "r"(b1));
                }
            }
        }
        __syncthreads();
    }

#pragma unroll
    for (int ma = 0; ma < 2; ma++) {
#pragma unroll
        for (int na = 0; na < 4; na++) {
            int gmb = m0 + wm + ma * 16 + grp;
            int gnb = n0 + wn + na * 8 + 2 * four;
#pragma unroll
            for (int q = 0; q < 4; q++) {
                int gm = gmb + (q >> 1) * 8;
                int gn = gnb + (q & 1);
                if (gm >= M || gn >= N) continue;
                float v = acc[ma][na][q];
                if (bias) v += bias[bz * sBias + gn];
                if (epi == 1) v *= RSQ;
                else if (epi == 2) v = (1.f - v) * RSQ;
                C[(long long)gm * ldc + gn] = v;
            }
        }
    }
}

// ------------------------- fused all-timestep LSTM --------------------------
// EW gather decoupled from the recurrent accumulation so the 56 scattered LDGs
// overlap the 5600-FMA m-loop instead of stalling it.
__global__ void __launch_bounds__(256, 1)
lstm_all(const int* __restrict__ rsent, const int* __restrict__ body,
         const float* __restrict__ whf, const float* __restrict__ whb,
         const float* __restrict__ bihf, const float* __restrict__ bhhf,
         const float* __restrict__ bihb, const float* __restrict__ bhhb)
{
    extern __shared__ float sh[];
    float* Wsh = sh;                    // [100][401]
    float* hT  = sh + 40100;            // [100][33]
    float* bcs = sh + 43400;            // [400]
    int*   toks = (int*)(sh + 43800);   // [28]

    int dir = blockIdx.y;
    int n0 = blockIdx.x * RPB;
    int tid = threadIdx.x;

    const float* wh = dir ? whb : whf;
    const float* bi = dir ? bihb : bihf;
    const float* bh = dir ? bhhb : bhhf;

    for (int e = tid; e < 40000; e += 256) {
        int j = e / 100, m = e - j * 100;
        Wsh[m * 401 + j] = wh[e];
    }
    for (int j = tid; j < 400; j += 256) bcs[j] = bi[j] + bh[j];
    for (int e = tid; e < 3300; e += 256) hT[e] = 0.f;

    int m2 = tid & 127;
    int half = tid >> 7;
    int rbase = half * RH;
    bool act = (m2 < 100);

    // preload step-0 tokens
    if (tid < RPB) {
        int w0 = dir ? 63 : 0;
        int n = n0 + tid;
        if (n >= NB) n = NB - 1;
        toks[tid] = (n == 0) ? rsent[w0] : body[(n - 1) * W_ + w0];
    }
    __syncthreads();

    float bj[4];
    if (act) {
#pragma unroll
        for (int jo = 0; jo < 4; jo++) bj[jo] = bcs[m2 + jo * 100];
    }

    float c[RH];
#pragma unroll
    for (int r = 0; r < RH; r++) c[r] = 0.f;

    for (int t = 0; t < 64; t++) {
        float ew[4][RH];
        float acc[4][RH];
        if (act) {
            // issue gathers first; they scoreboard-overlap the m-loop below
#pragma unroll
            for (int jo = 0; jo < 4; jo++) {
                int j = m2 + jo * 100;
#pragma unroll
                for (int r = 0; r < RH; r++)
                    ew[jo][r] = g_EW[(long long)toks[rbase + r] * 800 + dir * 400 + j];
            }
#pragma unroll
            for (int jo = 0; jo < 4; jo++)
#pragma unroll
                for (int r = 0; r < RH; r++) acc[jo][r] = 0.f;

            for (int m = 0; m < 100; m++) {
                float w0 = Wsh[m * 401 + m2];
                float w1 = Wsh[m * 401 + m2 + 100];
                float w2 = Wsh[m * 401 + m2 + 200];
                float w3 = Wsh[m * 401 + m2 + 300];
#pragma unroll
                for (int r = 0; r < RH; r++) {
                    float hv = hT[m * 33 + rbase + r];
                    acc[0][r] += w0 * hv;
                    acc[1][r] += w1 * hv;
                    acc[2][r] += w2 * hv;
                    acc[3][r] += w3 * hv;
                }
            }
        }
        __syncthreads();   // hT + toks reads done
        if (act) {
#pragma unroll
            for (int r = 0; r < RH; r++) {
                float gi = acc[0][r] + ew[0][r] + bj[0];
                float gf = acc[1][r] + ew[1][r] + bj[1];
                float gg = acc[2][r] + ew[2][r] + bj[2];
                float go = acc[3][r] + ew[3][r] + bj[3];
                float fi = 1.f / (1.f + expf(-gi));
                float ff = 1.f / (1.f + expf(-gf));
                float fo = 1.f / (1.f + expf(-go));
                c[r] = ff * c[r] + fi * tanhf(gg);
                hT[m2 * 33 + rbase + r] = fo * tanhf(c[r]);
            }
        }
        int tn = t + 1;
        if (tn < 64 && tid < RPB) {
            int w = dir ? (63 - tn) : tn;
            int n = n0 + tid;
            if (n >= NB) n = NB - 1;
            toks[tid] = (n == 0) ? rsent[w] : body[(n - 1) * W_ + w];
        }
        __syncthreads();   // new hT + toks visible
    }

    if (act) {
#pragma unroll
        for (int r = 0; r < RH; r++) {
            int n = n0 + rbase + r;
            if (n < NB) g_hid[n * D2_ + dir * M_ + m2] = hT[m2 * 33 + rbase + r];
        }
    }
}

// ----------------------------- sim / partition -----------------------------
__global__ void hv_k(const float* __restrict__ simw)
{
    int warp = threadIdx.x >> 5, lane = threadIdx.x & 31;
    int b = blockIdx.x * 32 + warp;
    if (b >= D2_) return;
    float a = 0.f;
    for (int i = lane; i < D2_; i += 32) a += g_hid[i] * simw[i * D2_ + b];
#pragma unroll
    for (int o = 16; o; o >>= 1) a += __shfl_down_sync(0xffffffffu, a, o);
    if (lane == 0) g_hv[b] = a;
}

__global__ void logits_k(const float* __restrict__ simb)
{
    __shared__ float hv[D2_];
    int tid = threadIdx.x;
    if (tid < D2_) hv[tid] = g_hv[tid];
    __syncthreads();
    int warp = tid >> 5, lane = tid & 31;
    int s = blockIdx.x * 8 + warp;
    const float* row = g_hid + (long long)(s + 1) * D2_;
    float a = 0.f;
    for (int b = lane; b < D2_; b += 32) a += hv[b] * row[b];
#pragma unroll
    for (int o = 16; o; o >>= 1) a += __shfl_down_sync(0xffffffffu, a, o);
    if (lane == 0) g_logit[s] = a + simb[0];
}

__global__ void softpart()
{
    __shared__ float sg[S_];
    __shared__ float redm[32];
    __shared__ float reds[32];
    __shared__ int cnt[1024];
    int tid = threadIdx.x;           // 1024
    for (int s = tid; s < S_; s += 1024) {
        float l = g_logit[s];
        sg[s] = 1.f / (1.f + expf(-l));
    }
    __syncthreads();
    float m = fmaxf(sg[tid], sg[tid + 1024]);
#pragma unroll
    for (int o = 16; o; o >>= 1) m = fmaxf(m, __shfl_xor_sync(0xffffffffu, m, o));
    if ((tid & 31) == 0) redm[tid >> 5] = m;
    __syncthreads();
    if (tid < 32) {
        float v = redm[tid];
#pragma unroll
        for (int o = 16; o; o >>= 1) v = fmaxf(v, __shfl_xor_sync(0xffffffffu, v, o));
        if (tid == 0) redm[0] = v;
    }
    __syncthreads();
    float mx = redm[0];
    float z = expf(sg[tid] - mx) + expf(sg[tid + 1024] - mx);
#pragma unroll
    for (int o = 16; o; o >>= 1) z += __shfl_xor_sync(0xffffffffu, z, o);
    if ((tid & 31) == 0) reds[tid >> 5] = z;
    __syncthreads();
    if (tid < 32) {
        float v = reds[tid];
#pragma unroll
        for (int o = 16; o; o >>= 1) v += __shfl_xor_sync(0xffffffffu, v, o);
        if (tid == 0) reds[0] = v;
    }
    __syncthreads();
    float invZ = 1.f / reds[0];
    for (int s = tid; s < S_; s += 1024) g_prob[s] = expf(sg[s] - mx) * invZ;

    int a = (sg[2 * tid] >= 0.5f) ? 1 : 0;
    int b = (sg[2 * tid + 1] >= 0.5f) ? 1 : 0;
    cnt[tid] = a + b;
    __syncthreads();
    for (int off = 1; off < 1024; off <<= 1) {
        int v = cnt[tid];
        int u = (tid >= off) ? cnt[tid - off] : 0;
        __syncthreads();
        cnt[tid] = v + u;
        __syncthreads();
    }
    int pre = (tid > 0) ? cnt[tid - 1] : 0;
    int tot = cnt[1023];
    int s0 = 2 * tid, s1 = 2 * tid + 1;
    if (a) g_idx[0][pre] = s0; else g_idx[1][s0 - pre] = s0;
    int pre1 = pre + a;
    if (b) g_idx[0][pre1] = s1; else g_idx[1][s1 - pre1] = s1;
    if (tid == 0) { g_n[0] = tot; g_n[1] = S_ - tot; }
}

__global__ void attend_k()
{
    int e = blockIdx.x * 256 + threadIdx.x;
    if (e >= S_ * D2_) return;
    int s = e / D2_;
    g_att[e] = g_prob[s] * g_hid[e + D2_];
}

// -------------------------- branch-local kernels ---------------------------
__global__ void compact(int br)
{
    int p = blockIdx.x;
    if (p >= g_n[br]) return;
    int src = g_idx[br][p];
    for (int e = threadIdx.x; e < H_ * D2_; e += 192) {
        int h = e / D2_, o = e - h * D2_;
        long long di = (long long)h * (S_ * D2_) + (long long)p * D2_ + o;
        long long si = (long long)h * (S_ * D2_) + (long long)src * D2_ + o;
        g_Qc[di] = g_Qa[si];
        g_Kc[di] = g_Ka[si];
        g_Vc[di] = g_Va[si];
    }
}

__global__ void colstats(int br)
{
    int n = g_n[br];
    int t = blockIdx.x * 128 + threadIdx.x;
    if (t >= n) return;
    int h = blockIdx.y;
    const float* base = g_SC + (long long)h * S_ * S_ + t;
    float m = -1e30f;
    for (int s = 0; s < n; s++) m = fmaxf(m, base[(long long)s * S_]);
    float z = 0.f;
    for (int s = 0; s < n; s++) z += expf(base[(long long)s * S_] - m);
    g_mx[h * S_ + t] = m;
    g_iZ[h * S_ + t] = 1.f / z;
}

__global__ void pnorm(int br)
{
    int n = g_n[br];
    int s = blockIdx.y;
    if (s >= n) return;
    int capn = (n + 15) & ~15;
    int t = blockIdx.x * 256 + threadIdx.x;
    if (t >= capn) return;
    int h = blockIdx.z;
    long long ix = (long long)h * S_ * S_ + (long long)s * S_ + t;
    float v = 0.f;
    if (t < n) v = expf(g_SC[ix] - g_mx[h * S_ + t]) * g_iZ[h * S_ + t];
    g_SC[ix] = v;
}

__global__ void featpart(const float* __restrict__ fw, int br)
{
    int n = g_n[br];
    int j = blockIdx.x;
    int ch = blockIdx.y;
    int per = (n + 7) / 8;
    int s0 = ch * per;
    int s1 = s0 + per; if (s1 > n) s1 = n;
    if (s0 > n) s0 = n;
    float acc = 0.f;
    const float* base = fw + (long long)j * (S_ * D2_);
    for (long long e = (long long)s0 * D2_ + threadIdx.x; e < (long long)s1 * D2_; e += 256)
        acc += g_mh[e] * base[e];
    __shared__ float red[8];
#pragma unroll
    for (int o = 16; o; o >>= 1) acc += __shfl_xor_sync(0xffffffffu, acc, o);
    if ((threadIdx.x & 31) == 0) red[threadIdx.x >> 5] = acc;
    __syncthreads();
    if (threadIdx.x < 8) {
        float v = red[threadIdx.x];
#pragma unroll
        for (int o = 4; o; o >>= 1) v += __shfl_xor_sync(0x000000ffu, v, o);
        if (threadIdx.x == 0) g_fp[(br * 8 + ch) * D2_ + j] = v;
    }
}

__global__ void finalize(const float* __restrict__ fb, float* __restrict__ out)
{
    int i = blockIdx.x * 256 + threadIdx.x;
    if (i >= 400) return;
    int br = i / 200, j = i - br * 200;
    float a = fb[j];
    for (int c = 0; c < 8; c++) a += g_fp[(br * 8 + c) * D2_ + j];
    out[i] = a;
}

// --------------------------------- launcher --------------------------------
extern "C" void kernel_launch(void* const* d_in, const int* in_sizes, int n_in,
                              void* d_out, int out_size)
{
    const int*   rsent = (const int*)d_in[0];
    const int*   body  = (const int*)d_in[1];
    const float* emb   = (const float*)d_in[2];
    const float* wihf  = (const float*)d_in[3];
    const float* whhf  = (const float*)d_in[4];
    const float* bihf  = (const float*)d_in[5];
    const float* bhhf  = (const float*)d_in[6];
    const float* wihb  = (const float*)d_in[7];
    const float* whhb  = (const float*)d_in[8];
    const float* bihb  = (const float*)d_in[9];
    const float* bhhb  = (const float*)d_in[10];
    const float* simw  = (const float*)d_in[11];
    const float* simb  = (const float*)d_in[12];
    const float* qw    = (const float*)d_in[13];
    const float* qb    = (const float*)d_in[14];
    const float* kw    = (const float*)d_in[15];
    const float* kb    = (const float*)d_in[16];
    const float* vw    = (const float*)d_in[17];
    const float* vb    = (const float*)d_in[18];
    const float* cw    = (const float*)d_in[19];
    const float* cb    = (const float*)d_in[20];
    const float* fw    = (const float*)d_in[21];
    const float* fb    = (const float*)d_in[22];
    float* out = (float*)d_out;

    float *pEW, *pAtt, *pQa, *pKa, *pVa, *pQc, *pKc, *pVc, *pSC, *pCat, *pMh;
    cudaGetSymbolAddress((void**)&pEW, g_EW);
    cudaGetSymbolAddress((void**)&pAtt, g_att);
    cudaGetSymbolAddress((void**)&pQa, g_Qa);
    cudaGetSymbolAddress((void**)&pKa, g_Ka);
    cudaGetSymbolAddress((void**)&pVa, g_Va);
    cudaGetSymbolAddress((void**)&pQc, g_Qc);
    cudaGetSymbolAddress((void**)&pKc, g_Kc);
    cudaGetSymbolAddress((void**)&pVc, g_Vc);
    cudaGetSymbolAddress((void**)&pSC, g_SC);
    cudaGetSymbolAddress((void**)&pCat, g_cat);
    cudaGetSymbolAddress((void**)&pMh, g_mh);

    // EW = emb @ w_ih^T  — now TF32 (mask-margin analysis: safe)
    dim3 ge(7, 391, 1);
    tgemm<<<ge, 256>>>(emb, 300, 0, wihf, 300, 0, 1, pEW,       800, 0,
                       V_, 400, 300, nullptr, 0, -1, 0, 0, 0, 0);
    tgemm<<<ge, 256>>>(emb, 300, 0, wihb, 300, 0, 1, pEW + 400, 800, 0,
                       V_, 400, 300, nullptr, 0, -1, 0, 0, 0, 0);

    const int SMEM_LSTM = (40100 + 3300 + 400) * 4 + RPB * 4;
    cudaFuncSetAttribute(lstm_all, cudaFuncAttributeMaxDynamicSharedMemorySize, SMEM_LSTM);
    lstm_all<<<dim3(74, 2), 256, SMEM_LSTM>>>(rsent, body, whhf, whhb,
                                              bihf, bhhf, bihb, bhhb);

    hv_k<<<7, 1024>>>(simw);
    logits_k<<<256, 256>>>(simb);
    softpart<<<1, 1024>>>();
    attend_k<<<1600, 256>>>();

    // Q/K/V on full attend, h-batched (z=8) — TF32 tensor path
    dim3 gq(4, 16, 8);
    tgemm<<<gq, 256>>>(pAtt, 200, 0, qw, 200, 40000LL, 1, pQa, 200, 409600LL,
                       S_, 200, 200, qb, 200, -1, 0, 0, 0, 0);
    tgemm<<<gq, 256>>>(pAtt, 200, 0, kw, 200, 40000LL, 1, pKa, 200, 409600LL,
                       S_, 200, 200, kb, 200, -1, 0, 0, 0, 0);
    tgemm<<<gq, 256>>>(pAtt, 200, 0, vw, 200, 40000LL, 1, pVa, 200, 409600LL,
                       S_, 200, 200, vb, 200, -1, 0, 0, 0, 0);

    for (int br = 0; br < 2; br++) {
        compact<<<2048, 192>>>(br);

        dim3 gs(32, 16, 8);
        tgemm<<<gs, 256>>>(pQc, 200, 409600LL, pKc, 200, 409600LL, 1,
                           pSC, 2048, 4194304LL, S_, S_, 200,
                           nullptr, 0, br, 1, 1, 0, (br == 0) ? 1 : 2);

        colstats<<<dim3(16, 8), 128>>>(br);
        pnorm<<<dim3(8, 2048, 8), 256>>>(br);

        dim3 go(4, 16, 8);
        tgemm<<<go, 256>>>(pSC, 2048, 4194304LL, pVc, 200, 409600LL, 0,
                           pCat, 1600, 200LL, S_, 200, S_,
                           nullptr, 0, br, 1, 0, 1, 0);

        dim3 gm(4, 16, 1);
        tgemm<<<gm, 256>>>(pCat, 1600, 0, cw, 1600, 0, 1, pMh, 200, 0,
                           S_, 200, 1600, cb, 0, br, 1, 0, 0, 0);

        featpart<<<dim3(200, 8), 256>>>(fw, br);
    }

    finalize<<<2, 256>>>(fb, out);
}

// round 14
// speedup vs baseline: 1.9648x; 1.0492x over previous
#include <cuda_runtime.h>
#include <math.h>

#define NB 2049
#define S_ 2048
#define W_ 64
#define D_ 300
#define M_ 100
#define H_ 8
#define D2_ 200
#define V_ 50000
#define RSQ 0.07071067811865475f   // 1/sqrt(200)

#define RPB 28                     // rows per LSTM block
#define RH 14                      // rows per thread-half

// ----------------------------- device scratch ------------------------------
__device__ float g_EW[V_ * 800];          // emb @ [w_ih_f | w_ih_b]^T
__device__ float g_hid[NB * D2_];         // [h_f | h_b]
__device__ float g_hv[D2_];
__device__ float g_logit[S_];
__device__ float g_prob[S_];
__device__ float g_att[S_ * D2_];
__device__ float g_Qa[H_ * S_ * D2_];
__device__ float g_Ka[H_ * S_ * D2_];
__device__ float g_Va[H_ * S_ * D2_];
__device__ float g_Qc[H_ * S_ * D2_];
__device__ float g_Kc[H_ * S_ * D2_];
__device__ float g_Vc[H_ * S_ * D2_];
__device__ float g_SC[33554432];          // 8 * 2048 * 2048: E = exp(scores)
__device__ float g_iZ[H_ * S_];
__device__ float g_cat[S_ * H_ * D2_];    // out in cat layout [s][h*200+o]
__device__ float g_mh[S_ * D2_];
__device__ float g_fp[2 * 8 * D2_];
__device__ int   g_idx[2][S_];
__device__ int   g_n[2];

__device__ __forceinline__ unsigned f2tf(float v) {
    unsigned r; asm("cvt.rna.tf32.f32 %0, %1;" : "=r"(r) : "f"(v)); return r;
}
// exp(x) for |x| < 0.3 : degree-4 Taylor (FMA pipe, avoids MUFU)
__device__ __forceinline__ float pexp(float x) {
    return 1.f + x * (1.f + x * (0.5f + x * (0.16666667f + x * 0.041666668f)));
}

// ------------- TF32 tensor GEMM, double-buffered (1 sync/iter) -------------
// C[M,N] = A[M,K]*op(B) (+bias). transB: B is (N,K). limBr>=0: lim=g_n[limBr];
// limRows/limCols skip tiles; capK caps K. epi: 1 v*RSQ; 2 (1-v)*RSQ;
// 3 pexp(v*RSQ); 4 pexp((1-v)*RSQ). aClampK: zero A cols with k>=lim.
// bScaleIZ: scale staged B (noT) rows by g_iZ[bz*S_+k].
#define BM 128
#define BN 64
#define BK 16
#define TASTR 137
#define TBSTR 73

__global__ void tgemm(const float* __restrict__ A, int lda, long long sA,
                      const float* __restrict__ B, int ldb, long long sB, int transB,
                      float* __restrict__ C, int ldc, long long sC,
                      int M, int N, int K,
                      const float* __restrict__ bias, int sBias,
                      int limBr, int limRows, int limCols, int capK, int epi,
                      int aClampK, int bScaleIZ)
{
    int bz = blockIdx.z;
    int m0 = blockIdx.y * BM;
    int n0 = blockIdx.x * BN;
    int lim = 0x7fffffff;
    if (limBr >= 0) {
        lim = g_n[limBr];
        if (limRows && m0 >= lim) return;
        if (limCols && n0 >= lim) return;
        if (capK) { int kc = (lim + 15) & ~15; if (kc < K) K = kc; }
    }
    int limA = aClampK ? lim : 0x7fffffff;
    const float* iZp = g_iZ + (long long)bz * S_;
    A += (long long)bz * sA;
    B += (long long)bz * sB;
    C += (long long)bz * sC;

    __shared__ __align__(16) float As[2][BK][TASTR];
    __shared__ __align__(16) float Bs[2][BK][TBSTR];

    int tid = threadIdx.x;            // 256 threads = 8 warps (4m x 2n)
    int lane = tid & 31;
    int wrp = tid >> 5;
    int wm = (wrp & 3) * 32;
    int wn = (wrp >> 2) * 32;
    int grp = lane >> 2;
    int four = lane & 3;

    float acc[2][4][4];
#pragma unroll
    for (int i = 0; i < 2; i++)
#pragma unroll
        for (int j = 0; j < 4; j++)
#pragma unroll
            for (int q = 0; q < 4; q++) acc[i][j][q] = 0.f;

    int am = tid >> 4;
    int ak = tid & 15;
    int bn = tid >> 4;
    int bk = tid & 15;
    int bk2 = tid >> 6;
    int bn2 = tid & 63;

    float ra[8], rb[4];
    // ---- prologue: load tile 0 ----
#pragma unroll
    for (int i = 0; i < 8; i++) {
        int gm = m0 + am + i * 16, gk = ak;
        ra[i] = (gm < M && gk < K && gk < limA) ? A[(long long)gm * lda + gk] : 0.f;
    }
    if (transB) {
#pragma unroll
        for (int i = 0; i < 4; i++) {
            int gn = n0 + bn + i * 16, gk = bk;
            rb[i] = (gn < N && gk < K) ? B[(long long)gn * ldb + gk] : 0.f;
        }
    } else {
#pragma unroll
        for (int i = 0; i < 4; i++) {
            int gk = bk2 + i * 4, gn = n0 + bn2;
            float v = (gk < K && gn < N) ? B[(long long)gk * ldb + gn] : 0.f;
            if (bScaleIZ && gk < K) v *= iZp[gk];
            rb[i] = v;
        }
    }

    int buf = 0;
    for (int k0 = 0; k0 < K; k0 += BK) {
        // commit regs to As[buf]/Bs[buf]
#pragma unroll
        for (int i = 0; i < 8; i++) As[buf][ak][am + i * 16] = __uint_as_float(f2tf(ra[i]));
        if (transB) {
#pragma unroll
            for (int i = 0; i < 4; i++) Bs[buf][bk][bn + i * 16] = __uint_as_float(f2tf(rb[i]));
        } else {
#pragma unroll
            for (int i = 0; i < 4; i++) Bs[buf][bk2 + i * 4][bn2] = __uint_as_float(f2tf(rb[i]));
        }
        __syncthreads();

        // prefetch next tile into registers (overlaps MMA)
        int kn = k0 + BK;
        if (kn < K) {
#pragma unroll
            for (int i = 0; i < 8; i++) {
                int gm = m0 + am + i * 16, gk = kn + ak;
                ra[i] = (gm < M && gk < K && gk < limA) ? A[(long long)gm * lda + gk] : 0.f;
            }
            if (transB) {
#pragma unroll
                for (int i = 0; i < 4; i++) {
                    int gn = n0 + bn + i * 16, gk = kn + bk;
                    rb[i] = (gn < N && gk < K) ? B[(long long)gn * ldb + gk] : 0.f;
                }
            } else {
#pragma unroll
                for (int i = 0; i < 4; i++) {
                    int gk = kn + bk2 + i * 4, gn = n0 + bn2;
                    float v = (gk < K && gn < N) ? B[(long long)gk * ldb + gn] : 0.f;
                    if (bScaleIZ && gk < K) v *= iZp[gk];
                    rb[i] = v;
                }
            }
        }

        // MMA on buffer `buf`
#pragma unroll
        for (int kk = 0; kk < BK; kk += 8) {
            unsigned a[2][4];
#pragma unroll
            for (int ma = 0; ma < 2; ma++) {
                int mb = wm + ma * 16 + grp;
                a[ma][0] = __float_as_uint(As[buf][kk + four][mb]);
                a[ma][1] = __float_as_uint(As[buf][kk + four][mb + 8]);
                a[ma][2] = __float_as_uint(As[buf][kk + 4 + four][mb]);
                a[ma][3] = __float_as_uint(As[buf][kk + 4 + four][mb + 8]);
            }
#pragma unroll
            for (int na = 0; na < 4; na++) {
                int nb = wn + na * 8 + grp;
                unsigned b0 = __float_as_uint(Bs[buf][kk + four][nb]);
                unsigned b1 = __float_as_uint(Bs[buf][kk + 4 + four][nb]);
#pragma unroll
                for (int ma = 0; ma < 2; ma++) {
                    asm("mma.sync.aligned.m16n8k8.row.col.f32.tf32.tf32.f32 "
                        "{%0,%1,%2,%3}, {%4,%5,%6,%7}, {%8,%9}, {%0,%1,%2,%3};"
                        : "+f"(acc[ma][na][0]), "+f"(acc[ma][na][1]),
                          "+f"(acc[ma][na][2]), "+f"(acc[ma][na][3])
                        : "r"(a[ma][0]), "r"(a[ma][1]), "r"(a[ma][2]), "r"(a[ma][3]),
                          "r"(b0), "r"(b1));
                }
            }
        }
        buf ^= 1;
    }

#pragma unroll
    for (int ma = 0; ma < 2; ma++) {
#pragma unroll
        for (int na = 0; na < 4; na++) {
            int gmb = m0 + wm + ma * 16 + grp;
            int gnb = n0 + wn + na * 8 + 2 * four;
#pragma unroll
            for (int q = 0; q < 4; q++) {
                int gm = gmb + (q >> 1) * 8;
                int gn = gnb + (q & 1);
                if (gm >= M || gn >= N) continue;
                float v = acc[ma][na][q];
                if (bias) v += bias[bz * sBias + gn];
                if (epi == 1) v *= RSQ;
                else if (epi == 2) v = (1.f - v) * RSQ;
                else if (epi == 3) v = pexp(v * RSQ);
                else if (epi == 4) v = pexp((1.f - v) * RSQ);
                C[(long long)gm * ldc + gn] = v;
            }
        }
    }
}

// ------------------------- fused all-timestep LSTM --------------------------
__global__ void __launch_bounds__(256, 1)
lstm_all(const int* __restrict__ rsent, const int* __restrict__ body,
         const float* __restrict__ whf, const float* __restrict__ whb,
         const float* __restrict__ bihf, const float* __restrict__ bhhf,
         const float* __restrict__ bihb, const float* __restrict__ bhhb)
{
    extern __shared__ float sh[];
    float* Wsh = sh;                    // [100][401]
    float* hT  = sh + 40100;            // [100][33]
    float* bcs = sh + 43400;            // [400]
    int*   toks = (int*)(sh + 43800);   // [28]

    int dir = blockIdx.y;
    int n0 = blockIdx.x * RPB;
    int tid = threadIdx.x;

    const float* wh = dir ? whb : whf;
    const float* bi = dir ? bihb : bihf;
    const float* bh = dir ? bhhb : bhhf;

    for (int e = tid; e < 40000; e += 256) {
        int j = e / 100, m = e - j * 100;
        Wsh[m * 401 + j] = wh[e];
    }
    for (int j = tid; j < 400; j += 256) bcs[j] = bi[j] + bh[j];
    for (int e = tid; e < 3300; e += 256) hT[e] = 0.f;

    int m2 = tid & 127;
    int half = tid >> 7;
    int rbase = half * RH;
    bool act = (m2 < 100);

    if (tid < RPB) {
        int w0 = dir ? 63 : 0;
        int n = n0 + tid;
        if (n >= NB) n = NB - 1;
        toks[tid] = (n == 0) ? rsent[w0] : body[(n - 1) * W_ + w0];
    }
    __syncthreads();

    float bj[4];
    if (act) {
#pragma unroll
        for (int jo = 0; jo < 4; jo++) bj[jo] = bcs[m2 + jo * 100];
    }

    float c[RH];
#pragma unroll
    for (int r = 0; r < RH; r++) c[r] = 0.f;

    for (int t = 0; t < 64; t++) {
        float ew[4][RH];
        float acc[4][RH];
        if (act) {
#pragma unroll
            for (int jo = 0; jo < 4; jo++) {
                int j = m2 + jo * 100;
#pragma unroll
                for (int r = 0; r < RH; r++)
                    ew[jo][r] = g_EW[(long long)toks[rbase + r] * 800 + dir * 400 + j];
            }
#pragma unroll
            for (int jo = 0; jo < 4; jo++)
#pragma unroll
                for (int r = 0; r < RH; r++) acc[jo][r] = 0.f;

            for (int m = 0; m < 100; m++) {
                float w0 = Wsh[m * 401 + m2];
                float w1 = Wsh[m * 401 + m2 + 100];
                float w2 = Wsh[m * 401 + m2 + 200];
                float w3 = Wsh[m * 401 + m2 + 300];
#pragma unroll
                for (int r = 0; r < RH; r++) {
                    float hv = hT[m * 33 + rbase + r];
                    acc[0][r] += w0 * hv;
                    acc[1][r] += w1 * hv;
                    acc[2][r] += w2 * hv;
                    acc[3][r] += w3 * hv;
                }
            }
        }
        __syncthreads();
        if (act) {
#pragma unroll
            for (int r = 0; r < RH; r++) {
                float gi = acc[0][r] + ew[0][r] + bj[0];
                float gf = acc[1][r] + ew[1][r] + bj[1];
                float gg = acc[2][r] + ew[2][r] + bj[2];
                float go = acc[3][r] + ew[3][r] + bj[3];
                float fi = 1.f / (1.f + expf(-gi));
                float ff = 1.f / (1.f + expf(-gf));
                float fo = 1.f / (1.f + expf(-go));
                c[r] = ff * c[r] + fi * tanhf(gg);
                hT[m2 * 33 + rbase + r] = fo * tanhf(c[r]);
            }
        }
        int tn = t + 1;
        if (tn < 64 && tid < RPB) {
            int w = dir ? (63 - tn) : tn;
            int n = n0 + tid;
            if (n >= NB) n = NB - 1;
            toks[tid] = (n == 0) ? rsent[w] : body[(n - 1) * W_ + w];
        }
        __syncthreads();
    }

    if (act) {
#pragma unroll
        for (int r = 0; r < RH; r++) {
            int n = n0 + rbase + r;
            if (n < NB) g_hid[n * D2_ + dir * M_ + m2] = hT[m2 * 33 + rbase + r];
        }
    }
}

// ----------------------------- sim / partition -----------------------------
__global__ void hv_k(const float* __restrict__ simw)
{
    int warp = threadIdx.x >> 5, lane = threadIdx.x & 31;
    int b = blockIdx.x * 32 + warp;
    if (b >= D2_) return;
    float a = 0.f;
    for (int i = lane; i < D2_; i += 32) a += g_hid[i] * simw[i * D2_ + b];
#pragma unroll
    for (int o = 16; o; o >>= 1) a += __shfl_down_sync(0xffffffffu, a, o);
    if (lane == 0) g_hv[b] = a;
}

__global__ void logits_k(const float* __restrict__ simb)
{
    __shared__ float hv[D2_];
    int tid = threadIdx.x;
    if (tid < D2_) hv[tid] = g_hv[tid];
    __syncthreads();
    int warp = tid >> 5, lane = tid & 31;
    int s = blockIdx.x * 8 + warp;
    const float* row = g_hid + (long long)(s + 1) * D2_;
    float a = 0.f;
    for (int b = lane; b < D2_; b += 32) a += hv[b] * row[b];
#pragma unroll
    for (int o = 16; o; o >>= 1) a += __shfl_down_sync(0xffffffffu, a, o);
    if (lane == 0) g_logit[s] = a + simb[0];
}

__global__ void softpart()
{
    __shared__ float sg[S_];
    __shared__ float redm[32];
    __shared__ float reds[32];
    __shared__ int cnt[1024];
    int tid = threadIdx.x;           // 1024
    for (int s = tid; s < S_; s += 1024) {
        float l = g_logit[s];
        sg[s] = 1.f / (1.f + expf(-l));
    }
    __syncthreads();
    float m = fmaxf(sg[tid], sg[tid + 1024]);
#pragma unroll
    for (int o = 16; o; o >>= 1) m = fmaxf(m, __shfl_xor_sync(0xffffffffu, m, o));
    if ((tid & 31) == 0) redm[tid >> 5] = m;
    __syncthreads();
    if (tid < 32) {
        float v = redm[tid];
#pragma unroll
        for (int o = 16; o; o >>= 1) v = fmaxf(v, __shfl_xor_sync(0xffffffffu, v, o));
        if (tid == 0) redm[0] = v;
    }
    __syncthreads();
    float mx = redm[0];
    float z = expf(sg[tid] - mx) + expf(sg[tid + 1024] - mx);
#pragma unroll
    for (int o = 16; o; o >>= 1) z += __shfl_xor_sync(0xffffffffu, z, o);
    if ((tid & 31) == 0) reds[tid >> 5] = z;
    __syncthreads();
    if (tid < 32) {
        float v = reds[tid];
#pragma unroll
        for (int o = 16; o; o >>= 1) v += __shfl_xor_sync(0xffffffffu, v, o);
        if (tid == 0) reds[0] = v;
    }
    __syncthreads();
    float invZ = 1.f / reds[0];
    for (int s = tid; s < S_; s += 1024) g_prob[s] = expf(sg[s] - mx) * invZ;

    int a = (sg[2 * tid] >= 0.5f) ? 1 : 0;
    int b = (sg[2 * tid + 1] >= 0.5f) ? 1 : 0;
    cnt[tid] = a + b;
    __syncthreads();
    for (int off = 1; off < 1024; off <<= 1) {
        int v = cnt[tid];
        int u = (tid >= off) ? cnt[tid - off] : 0;
        __syncthreads();
        cnt[tid] = v + u;
        __syncthreads();
    }
    int pre = (tid > 0) ? cnt[tid - 1] : 0;
    int tot = cnt[1023];
    int s0 = 2 * tid, s1 = 2 * tid + 1;
    if (a) g_idx[0][pre] = s0; else g_idx[1][s0 - pre] = s0;
    int pre1 = pre + a;
    if (b) g_idx[0][pre1] = s1; else g_idx[1][s1 - pre1] = s1;
    if (tid == 0) { g_n[0] = tot; g_n[1] = S_ - tot; }
}

__global__ void attend_k()
{
    int e = blockIdx.x * 256 + threadIdx.x;
    if (e >= S_ * D2_) return;
    int s = e / D2_;
    g_att[e] = g_prob[s] * g_hid[e + D2_];
}

// -------------------------- branch-local kernels ---------------------------
__global__ void compact(int br)
{
    int p = blockIdx.x;
    if (p >= g_n[br]) return;
    int src = g_idx[br][p];
    for (int e = threadIdx.x; e < H_ * D2_; e += 192) {
        int h = e / D2_, o = e - h * D2_;
        long long di = (long long)h * (S_ * D2_) + (long long)p * D2_ + o;
        long long si = (long long)h * (S_ * D2_) + (long long)src * D2_ + o;
        g_Qc[di] = g_Qa[si];
        g_Kc[di] = g_Ka[si];
        g_Vc[di] = g_Va[si];
    }
}

// column sums of E (no max-subtraction needed: |scores·RSQ| << 1)
__global__ void colsum(int br)
{
    int n = g_n[br];
    int t = blockIdx.x * 128 + threadIdx.x;
    if (t >= n) return;
    int h = blockIdx.y;
    const float* base = g_SC + (long long)h * S_ * S_ + t;
    float z = 0.f;
    int s = 0;
    for (; s + 4 <= n; s += 4) {
        float v0 = base[(long long)s * S_];
        float v1 = base[(long long)(s + 1) * S_];
        float v2 = base[(long long)(s + 2) * S_];
        float v3 = base[(long long)(s + 3) * S_];
        z += (v0 + v1) + (v2 + v3);
    }
    for (; s < n; s++) z += base[(long long)s * S_];
    g_iZ[h * S_ + t] = 1.f / z;
}

__global__ void featpart(const float* __restrict__ fw, int br)
{
    int n = g_n[br];
    int j = blockIdx.x;
    int ch = blockIdx.y;
    int per = (n + 7) / 8;
    int s0 = ch * per;
    int s1 = s0 + per; if (s1 > n) s1 = n;
    if (s0 > n) s0 = n;
    float acc = 0.f;
    const float* base = fw + (long long)j * (S_ * D2_);
    for (long long e = (long long)s0 * D2_ + threadIdx.x; e < (long long)s1 * D2_; e += 256)
        acc += g_mh[e] * base[e];
    __shared__ float red[8];
#pragma unroll
    for (int o = 16; o; o >>= 1) acc += __shfl_xor_sync(0xffffffffu, acc, o);
    if ((threadIdx.x & 31) == 0) red[threadIdx.x >> 5] = acc;
    __syncthreads();
    if (threadIdx.x < 8) {
        float v = red[threadIdx.x];
#pragma unroll
        for (int o = 4; o; o >>= 1) v += __shfl_xor_sync(0x000000ffu, v, o);
        if (threadIdx.x == 0) g_fp[(br * 8 + ch) * D2_ + j] = v;
    }
}

__global__ void finalize(const float* __restrict__ fb, float* __restrict__ out)
{
    int i = blockIdx.x * 256 + threadIdx.x;
    if (i >= 400) return;
    int br = i / 200, j = i - br * 200;
    float a = fb[j];
    for (int c = 0; c < 8; c++) a += g_fp[(br * 8 + c) * D2_ + j];
    out[i] = a;
}

// --------------------------------- launcher --------------------------------
extern "C" void kernel_launch(void* const* d_in, const int* in_sizes, int n_in,
                              void* d_out, int out_size)
{
    const int*   rsent = (const int*)d_in[0];
    const int*   body  = (const int*)d_in[1];
    const float* emb   = (const float*)d_in[2];
    const float* wihf  = (const float*)d_in[3];
    const float* whhf  = (const float*)d_in[4];
    const float* bihf  = (const float*)d_in[5];
    const float* bhhf  = (const float*)d_in[6];
    const float* wihb  = (const float*)d_in[7];
    const float* whhb  = (const float*)d_in[8];
    const float* bihb  = (const float*)d_in[9];
    const float* bhhb  = (const float*)d_in[10];
    const float* simw  = (const float*)d_in[11];
    const float* simb  = (const float*)d_in[12];
    const float* qw    = (const float*)d_in[13];
    const float* qb    = (const float*)d_in[14];
    const float* kw    = (const float*)d_in[15];
    const float* kb    = (const float*)d_in[16];
    const float* vw    = (const float*)d_in[17];
    const float* vb    = (const float*)d_in[18];
    const float* cw    = (const float*)d_in[19];
    const float* cb    = (const float*)d_in[20];
    const float* fw    = (const float*)d_in[21];
    const float* fb    = (const float*)d_in[22];
    float* out = (float*)d_out;

    float *pEW, *pAtt, *pQa, *pKa, *pVa, *pQc, *pKc, *pVc, *pSC, *pCat, *pMh;
    cudaGetSymbolAddress((void**)&pEW, g_EW);
    cudaGetSymbolAddress((void**)&pAtt, g_att);
    cudaGetSymbolAddress((void**)&pQa, g_Qa);
    cudaGetSymbolAddress((void**)&pKa, g_Ka);
    cudaGetSymbolAddress((void**)&pVa, g_Va);
    cudaGetSymbolAddress((void**)&pQc, g_Qc);
    cudaGetSymbolAddress((void**)&pKc, g_Kc);
    cudaGetSymbolAddress((void**)&pVc, g_Vc);
    cudaGetSymbolAddress((void**)&pSC, g_SC);
    cudaGetSymbolAddress((void**)&pCat, g_cat);
    cudaGetSymbolAddress((void**)&pMh, g_mh);

    // EW = emb @ w_ih^T (TF32)
    dim3 ge(7, 391, 1);
    tgemm<<<ge, 256>>>(emb, 300, 0, wihf, 300, 0, 1, pEW,       800, 0,
                       V_, 400, 300, nullptr, 0, -1, 0, 0, 0, 0, 0, 0);
    tgemm<<<ge, 256>>>(emb, 300, 0, wihb, 300, 0, 1, pEW + 400, 800, 0,
                       V_, 400, 300, nullptr, 0, -1, 0, 0, 0, 0, 0, 0);

    const int SMEM_LSTM = (40100 + 3300 + 400) * 4 + RPB * 4;
    cudaFuncSetAttribute(lstm_all, cudaFuncAttributeMaxDynamicSharedMemorySize, SMEM_LSTM);
    lstm_all<<<dim3(74, 2), 256, SMEM_LSTM>>>(rsent, body, whhf, whhb,
                                              bihf, bhhf, bihb, bhhb);

    hv_k<<<7, 1024>>>(simw);
    logits_k<<<256, 256>>>(simb);
    softpart<<<1, 1024>>>();
    attend_k<<<1600, 256>>>();

    // Q/K/V on full attend, h-batched (z=8)
    dim3 gq(4, 16, 8);
    tgemm<<<gq, 256>>>(pAtt, 200, 0, qw, 200, 40000LL, 1, pQa, 200, 409600LL,
                       S_, 200, 200, qb, 200, -1, 0, 0, 0, 0, 0, 0);
    tgemm<<<gq, 256>>>(pAtt, 200, 0, kw, 200, 40000LL, 1, pKa, 200, 409600LL,
                       S_, 200, 200, kb, 200, -1, 0, 0, 0, 0, 0, 0);
    tgemm<<<gq, 256>>>(pAtt, 200, 0, vw, 200, 40000LL, 1, pVa, 200, 409600LL,
                       S_, 200, 200, vb, 200, -1, 0, 0, 0, 0, 0, 0);

    for (int br = 0; br < 2; br++) {
        compact<<<2048, 192>>>(br);

        // E[h,s,t] = exp(epi(Qc.Kc)) written directly by the GEMM epilogue
        dim3 gs(32, 16, 8);
        tgemm<<<gs, 256>>>(pQc, 200, 409600LL, pKc, 200, 409600LL, 1,
                           pSC, 2048, 4194304LL, S_, S_, 200,
                           nullptr, 0, br, 1, 1, 0, (br == 0) ? 4 : 3, 0, 0);

        colsum<<<dim3(16, 8), 128>>>(br);

        // out = E @ (iZ*V): A zero-clamped past n, B rows scaled by iZ in staging
        dim3 go(4, 16, 8);
        tgemm<<<go, 256>>>(pSC, 2048, 4194304LL, pVc, 200, 409600LL, 0,
                           pCat, 1600, 200LL, S_, 200, S_,
                           nullptr, 0, br, 1, 0, 1, 0, 1, 1);

        dim3 gm(4, 16, 1);
        tgemm<<<gm, 256>>>(pCat, 1600, 0, cw, 1600, 0, 1, pMh, 200, 0,
                           S_, 200, 1600, cb, 0, br, 1, 0, 0, 0, 0, 0);

        featpart<<<dim3(200, 8), 256>>>(fw, br);
    }

    finalize<<<2, 256>>>(fb, out);
}

// round 15
// speedup vs baseline: 2.1805x; 1.1097x over previous
#include <cuda_runtime.h>
#include <math.h>

#define NB 2049
#define S_ 2048
#define W_ 64
#define D_ 300
#define M_ 100
#define H_ 8
#define D2_ 200
#define V_ 50000
#define RSQ 0.07071067811865475f   // 1/sqrt(200)

#define RPB 28                     // rows per LSTM block
#define RH 14                      // rows per thread-half

// ----------------------------- device scratch ------------------------------
__device__ float g_EW[V_ * 800];          // emb @ [w_ih_f | w_ih_b]^T
__device__ float g_hid[NB * D2_];         // [h_f | h_b]
__device__ float g_hv[D2_];
__device__ float g_logit[S_];
__device__ float g_prob[S_];
__device__ float g_att[S_ * D2_];
__device__ float g_Qa[H_ * S_ * D2_];
__device__ float g_Ka[H_ * S_ * D2_];
__device__ float g_Va[H_ * S_ * D2_];
__device__ float g_Qc[H_ * S_ * D2_];
__device__ float g_Kc[H_ * S_ * D2_];
__device__ float g_Vc[H_ * S_ * D2_];
__device__ float g_SC[33554432];          // 8 * 2048 * 2048: E = exp(scores)
__device__ float g_iZ[H_ * S_];
__device__ float g_cat[S_ * H_ * D2_];    // out in cat layout [s][h*200+o]
__device__ float g_mh[S_ * D2_];
__device__ float g_fp[2 * 8 * D2_];
__device__ int   g_idx[2][S_];
__device__ int   g_n[2];

// exp(x) for |x| < 0.3 : degree-4 Taylor (FMA pipe, avoids MUFU)
__device__ __forceinline__ float pexp(float x) {
    return 1.f + x * (1.f + x * (0.5f + x * (0.16666667f + x * 0.041666668f)));
}

__device__ __forceinline__ unsigned sptr(const void* p) {
    return (unsigned)__cvta_generic_to_shared(p);
}
__device__ __forceinline__ void cpa16(unsigned dst, const void* src, int bytes) {
    asm volatile("cp.async.cg.shared.global [%0], [%1], 16, %2;\n"
                 :: "r"(dst), "l"(src), "r"(bytes));
}
__device__ __forceinline__ void cpa4(unsigned dst, const void* src, int bytes) {
    asm volatile("cp.async.ca.shared.global [%0], [%1], 4, %2;\n"
                 :: "r"(dst), "l"(src), "r"(bytes));
}
__device__ __forceinline__ void cpa_commit() {
    asm volatile("cp.async.commit_group;\n" ::: "memory");
}
__device__ __forceinline__ void cpa_wait0() {
    asm volatile("cp.async.wait_group 0;\n" ::: "memory");
}

// --------- TF32 tensor GEMM, cp.async double-buffered (1 sync/iter) --------
// C[M,N] = A[M,K]*op(B) (+bias). transB: B is (N,K). limBr>=0: lim=g_n[limBr];
// limRows/limCols skip tiles; capK caps K. epi: 1 v*RSQ; 2 (1-v)*RSQ;
// 3 pexp(v*RSQ); 4 pexp((1-v)*RSQ). aClampK: zero (zfill) A cols with k>=lim.
#define BM 128
#define BN 64
#define BK 16
#define ASTR2 20
#define BSTR2 72

__global__ void __launch_bounds__(256)
tgemm(const float* __restrict__ A, int lda, long long sA,
      const float* __restrict__ B, int ldb, long long sB, int transB,
      float* __restrict__ C, int ldc, long long sC,
      int M, int N, int K,
      const float* __restrict__ bias, int sBias,
      int limBr, int limRows, int limCols, int capK, int epi, int aClampK)
{
    int bz = blockIdx.z;
    int m0 = blockIdx.y * BM;
    int n0 = blockIdx.x * BN;
    int lim = 0x7fffffff;
    if (limBr >= 0) {
        lim = g_n[limBr];
        if (limRows && m0 >= lim) return;
        if (limCols && n0 >= lim) return;
        if (capK) { int kc = (lim + 15) & ~15; if (kc < K) K = kc; }
    }
    int limK = aClampK ? (lim < K ? lim : K) : K;
    A += (long long)bz * sA;
    B += (long long)bz * sB;
    C += (long long)bz * sC;

    __shared__ __align__(16) float As[2][BM][ASTR2];
    __shared__ __align__(16) float Bs[2][BK][BSTR2];

    int tid = threadIdx.x;            // 256 threads = 8 warps (4m x 2n)
    int lane = tid & 31;
    int wrp = tid >> 5;
    int wm = (wrp & 3) * 32;
    int wn = (wrp >> 2) * 32;
    int grp = lane >> 2;
    int four = lane & 3;

    // staging coordinates
    int sam = tid >> 2;               // A: m row (2 chunks: sam, sam+64)
    int sak = (tid & 3) * 4;          // A: k chunk base
    int sbn = tid >> 2;               // B transB: n row
    int sbk = (tid & 3) * 4;          // B transB: k chunk
    int sbk2 = tid >> 4;              // B noT: k row
    int sbn2 = (tid & 15) * 4;        // B noT: n chunk

    float acc[2][4][4];
#pragma unroll
    for (int i = 0; i < 2; i++)
#pragma unroll
        for (int j = 0; j < 4; j++)
#pragma unroll
            for (int q = 0; q < 4; q++) acc[i][j][q] = 0.f;

    unsigned asb[2] = { sptr(&As[0][0][0]), sptr(&As[1][0][0]) };
    unsigned bsb[2] = { sptr(&Bs[0][0][0]), sptr(&Bs[1][0][0]) };

    // ---- staging macro-ish lambdas ----
    auto stage = [&](int k0v, int b) {
        // A: 128 x 16 as [m][k], 16B ops with zfill
#pragma unroll
        for (int i = 0; i < 2; i++) {
            int m = sam + i * 64;
            int gm = m0 + m;
            int gk = k0v + sak;
            int rem = limK - gk; if (rem > 4) rem = 4; if (rem < 0) rem = 0;
            int bytes = (gm < M) ? rem * 4 : 0;
            int gms = (gm < M) ? gm : 0;
            cpa16(asb[b] + (m * ASTR2 + sak) * 4,
                  A + (long long)gms * lda + (gk < K ? gk : 0), bytes);
        }
        if (transB) {
            int gn = n0 + sbn;
            int gns = (gn < N) ? gn : 0;
#pragma unroll
            for (int j = 0; j < 4; j++) {
                int gk = k0v + sbk + j;
                int bytes = (gn < N && gk < K) ? 4 : 0;
                cpa4(bsb[b] + ((sbk + j) * BSTR2 + sbn) * 4,
                     B + (long long)gns * ldb + (gk < K ? gk : 0), bytes);
            }
        } else {
            int gk = k0v + sbk2;
            int gn = n0 + sbn2;
            int rem = N - gn; if (rem > 4) rem = 4; if (rem < 0) rem = 0;
            int bytes = (gk < K) ? rem * 4 : 0;
            cpa16(bsb[b] + (sbk2 * BSTR2 + sbn2) * 4,
                  B + (long long)(gk < K ? gk : 0) * ldb + (rem ? gn : 0), bytes);
        }
    };

    stage(0, 0);
    cpa_commit();

    int buf = 0;
    for (int k0v = 0; k0v < K; k0v += BK) {
        cpa_wait0();
        __syncthreads();
        int kn = k0v + BK;
        if (kn < K) { stage(kn, buf ^ 1); cpa_commit(); }

#pragma unroll
        for (int kk = 0; kk < BK; kk += 8) {
            unsigned a[2][4];
#pragma unroll
            for (int ma = 0; ma < 2; ma++) {
                int mb = wm + ma * 16 + grp;
                a[ma][0] = __float_as_uint(As[buf][mb][kk + four]);
                a[ma][1] = __float_as_uint(As[buf][mb + 8][kk + four]);
                a[ma][2] = __float_as_uint(As[buf][mb][kk + 4 + four]);
                a[ma][3] = __float_as_uint(As[buf][mb + 8][kk + 4 + four]);
            }
#pragma unroll
            for (int na = 0; na < 4; na++) {
                int nb = wn + na * 8 + grp;
                unsigned b0 = __float_as_uint(Bs[buf][kk + four][nb]);
                unsigned b1 = __float_as_uint(Bs[buf][kk + 4 + four][nb]);
#pragma unroll
                for (int ma = 0; ma < 2; ma++) {
                    asm("mma.sync.aligned.m16n8k8.row.col.f32.tf32.tf32.f32 "
                        "{%0,%1,%2,%3}, {%4,%5,%6,%7}, {%8,%9}, {%0,%1,%2,%3};"
                        : "+f"(acc[ma][na][0]), "+f"(acc[ma][na][1]),
                          "+f"(acc[ma][na][2]), "+f"(acc[ma][na][3])
                        : "r"(a[ma][0]), "r"(a[ma][1]), "r"(a[ma][2]), "r"(a[ma][3]),
                          "r"(b0), "r"(b1));
                }
            }
        }
        buf ^= 1;
    }

#pragma unroll
    for (int ma = 0; ma < 2; ma++) {
#pragma unroll
        for (int na = 0; na < 4; na++) {
            int gmb = m0 + wm + ma * 16 + grp;
            int gnb = n0 + wn + na * 8 + 2 * four;
#pragma unroll
            for (int q = 0; q < 4; q++) {
                int gm = gmb + (q >> 1) * 8;
                int gn = gnb + (q & 1);
                if (gm >= M || gn >= N) continue;
                float v = acc[ma][na][q];
                if (bias) v += bias[bz * sBias + gn];
                if (epi == 1) v *= RSQ;
                else if (epi == 2) v = (1.f - v) * RSQ;
                else if (epi == 3) v = pexp(v * RSQ);
                else if (epi == 4) v = pexp((1.f - v) * RSQ);
                C[(long long)gm * ldc + gn] = v;
            }
        }
    }
}

// ------------------------- fused all-timestep LSTM --------------------------
// Gate weights packed as float4 per (m, m2): 1 LDS.128 replaces 4 LDS.32.
// hT read as broadcast float2 pairs (stride 34).
__global__ void __launch_bounds__(256, 1)
lstm_all(const int* __restrict__ rsent, const int* __restrict__ body,
         const float* __restrict__ whf, const float* __restrict__ whb,
         const float* __restrict__ bihf, const float* __restrict__ bhhf,
         const float* __restrict__ bihb, const float* __restrict__ bhhb)
{
    extern __shared__ float sh[];
    float* Wg  = sh;                    // [100][100] float4 gates (40000 floats)
    float* hT  = sh + 40000;            // [100][34]
    float* bcs = sh + 43400;            // [400]
    int*   toks = (int*)(sh + 43800);   // [28]

    int dir = blockIdx.y;
    int n0 = blockIdx.x * RPB;
    int tid = threadIdx.x;

    const float* wh = dir ? whb : whf;
    const float* bi = dir ? bihb : bihf;
    const float* bh = dir ? bhhb : bhhf;

    // Wg[m*400 + m2*4 + gate] = wh[(gate*100 + m2)*100 + m]
    for (int e = tid; e < 40000; e += 256) {
        int j = e / 100, m = e - j * 100;
        int gate = j / 100, m2s = j - gate * 100;
        Wg[m * 400 + m2s * 4 + gate] = wh[e];
    }
    for (int j = tid; j < 400; j += 256) bcs[j] = bi[j] + bh[j];
    for (int e = tid; e < 3400; e += 256) hT[e] = 0.f;

    int m2 = tid & 127;
    int half = tid >> 7;
    int rbase = half * RH;
    bool act = (m2 < 100);

    if (tid < RPB) {
        int w0 = dir ? 63 : 0;
        int n = n0 + tid;
        if (n >= NB) n = NB - 1;
        toks[tid] = (n == 0) ? rsent[w0] : body[(n - 1) * W_ + w0];
    }
    __syncthreads();

    float bj[4];
    if (act) {
#pragma unroll
        for (int jo = 0; jo < 4; jo++) bj[jo] = bcs[m2 + jo * 100];
    }

    float c[RH];
#pragma unroll
    for (int r = 0; r < RH; r++) c[r] = 0.f;

    for (int t = 0; t < 64; t++) {
        float ew[4][RH];
        float acc[4][RH];
        if (act) {
#pragma unroll
            for (int jo = 0; jo < 4; jo++) {
                int j = m2 + jo * 100;
#pragma unroll
                for (int r = 0; r < RH; r++)
                    ew[jo][r] = g_EW[(long long)toks[rbase + r] * 800 + dir * 400 + j];
            }
#pragma unroll
            for (int jo = 0; jo < 4; jo++)
#pragma unroll
                for (int r = 0; r < RH; r++) acc[jo][r] = 0.f;

            for (int m = 0; m < 100; m++) {
                float4 w = *reinterpret_cast<const float4*>(&Wg[m * 400 + m2 * 4]);
                const float2* hp = reinterpret_cast<const float2*>(&hT[m * 34 + rbase]);
#pragma unroll
                for (int p = 0; p < 7; p++) {
                    float2 hv = hp[p];
                    acc[0][2 * p]     += w.x * hv.x;
                    acc[0][2 * p + 1] += w.x * hv.y;
                    acc[1][2 * p]     += w.y * hv.x;
                    acc[1][2 * p + 1] += w.y * hv.y;
                    acc[2][2 * p]     += w.z * hv.x;
                    acc[2][2 * p + 1] += w.z * hv.y;
                    acc[3][2 * p]     += w.w * hv.x;
                    acc[3][2 * p + 1] += w.w * hv.y;
                }
            }
        }
        __syncthreads();
        if (act) {
#pragma unroll
            for (int r = 0; r < RH; r++) {
                float gi = acc[0][r] + ew[0][r] + bj[0];
                float gf = acc[1][r] + ew[1][r] + bj[1];
                float gg = acc[2][r] + ew[2][r] + bj[2];
                float go = acc[3][r] + ew[3][r] + bj[3];
                float fi = 1.f / (1.f + expf(-gi));
                float ff = 1.f / (1.f + expf(-gf));
                float fo = 1.f / (1.f + expf(-go));
                c[r] = ff * c[r] + fi * tanhf(gg);
                hT[m2 * 34 + rbase + r] = fo * tanhf(c[r]);
            }
        }
        int tn = t + 1;
        if (tn < 64 && tid < RPB) {
            int w = dir ? (63 - tn) : tn;
            int n = n0 + tid;
            if (n >= NB) n = NB - 1;
            toks[tid] = (n == 0) ? rsent[w] : body[(n - 1) * W_ + w];
        }
        __syncthreads();
    }

    if (act) {
#pragma unroll
        for (int r = 0; r < RH; r++) {
            int n = n0 + rbase + r;
            if (n < NB) g_hid[n * D2_ + dir * M_ + m2] = hT[m2 * 34 + rbase + r];
        }
    }
}

// ----------------------------- sim / partition -----------------------------
__global__ void hv_k(const float* __restrict__ simw)
{
    int warp = threadIdx.x >> 5, lane = threadIdx.x & 31;
    int b = blockIdx.x * 32 + warp;
    if (b >= D2_) return;
    float a = 0.f;
    for (int i = lane; i < D2_; i += 32) a += g_hid[i] * simw[i * D2_ + b];
#pragma unroll
    for (int o = 16; o; o >>= 1) a += __shfl_down_sync(0xffffffffu, a, o);
    if (lane == 0) g_hv[b] = a;
}

__global__ void logits_k(const float* __restrict__ simb)
{
    __shared__ float hv[D2_];
    int tid = threadIdx.x;
    if (tid < D2_) hv[tid] = g_hv[tid];
    __syncthreads();
    int warp = tid >> 5, lane = tid & 31;
    int s = blockIdx.x * 8 + warp;
    const float* row = g_hid + (long long)(s + 1) * D2_;
    float a = 0.f;
    for (int b = lane; b < D2_; b += 32) a += hv[b] * row[b];
#pragma unroll
    for (int o = 16; o; o >>= 1) a += __shfl_down_sync(0xffffffffu, a, o);
    if (lane == 0) g_logit[s] = a + simb[0];
}

__global__ void softpart()
{
    __shared__ float sg[S_];
    __shared__ float redm[32];
    __shared__ float reds[32];
    __shared__ int cnt[1024];
    int tid = threadIdx.x;           // 1024
    for (int s = tid; s < S_; s += 1024) {
        float l = g_logit[s];
        sg[s] = 1.f / (1.f + expf(-l));
    }
    __syncthreads();
    float m = fmaxf(sg[tid], sg[tid + 1024]);
#pragma unroll
    for (int o = 16; o; o >>= 1) m = fmaxf(m, __shfl_xor_sync(0xffffffffu, m, o));
    if ((tid & 31) == 0) redm[tid >> 5] = m;
    __syncthreads();
    if (tid < 32) {
        float v = redm[tid];
#pragma unroll
        for (int o = 16; o; o >>= 1) v = fmaxf(v, __shfl_xor_sync(0xffffffffu, v, o));
        if (tid == 0) redm[0] = v;
    }
    __syncthreads();
    float mx = redm[0];
    float z = expf(sg[tid] - mx) + expf(sg[tid + 1024] - mx);
#pragma unroll
    for (int o = 16; o; o >>= 1) z += __shfl_xor_sync(0xffffffffu, z, o);
    if ((tid & 31) == 0) reds[tid >> 5] = z;
    __syncthreads();
    if (tid < 32) {
        float v = reds[tid];
#pragma unroll
        for (int o = 16; o; o >>= 1) v += __shfl_xor_sync(0xffffffffu, v, o);
        if (tid == 0) reds[0] = v;
    }
    __syncthreads();
    float invZ = 1.f / reds[0];
    for (int s = tid; s < S_; s += 1024) g_prob[s] = expf(sg[s] - mx) * invZ;

    int a = (sg[2 * tid] >= 0.5f) ? 1 : 0;
    int b = (sg[2 * tid + 1] >= 0.5f) ? 1 : 0;
    cnt[tid] = a + b;
    __syncthreads();
    for (int off = 1; off < 1024; off <<= 1) {
        int v = cnt[tid];
        int u = (tid >= off) ? cnt[tid - off] : 0;
        __syncthreads();
        cnt[tid] = v + u;
        __syncthreads();
    }
    int pre = (tid > 0) ? cnt[tid - 1] : 0;
    int tot = cnt[1023];
    int s0 = 2 * tid, s1 = 2 * tid + 1;
    if (a) g_idx[0][pre] = s0; else g_idx[1][s0 - pre] = s0;
    int pre1 = pre + a;
    if (b) g_idx[0][pre1] = s1; else g_idx[1][s1 - pre1] = s1;
    if (tid == 0) { g_n[0] = tot; g_n[1] = S_ - tot; }
}

__global__ void attend_k()
{
    int e = blockIdx.x * 256 + threadIdx.x;
    if (e >= S_ * D2_) return;
    int s = e / D2_;
    g_att[e] = g_prob[s] * g_hid[e + D2_];
}

// -------------------------- branch-local kernels ---------------------------
__global__ void compact(int br)
{
    int p = blockIdx.x;
    if (p >= g_n[br]) return;
    int src = g_idx[br][p];
    for (int e = threadIdx.x; e < H_ * D2_; e += 192) {
        int h = e / D2_, o = e - h * D2_;
        long long di = (long long)h * (S_ * D2_) + (long long)p * D2_ + o;
        long long si = (long long)h * (S_ * D2_) + (long long)src * D2_ + o;
        g_Qc[di] = g_Qa[si];
        g_Kc[di] = g_Ka[si];
        g_Vc[di] = g_Va[si];
    }
}

// column sums of E (no max-subtraction needed: |scores·RSQ| << 1)
__global__ void colsum(int br)
{
    int n = g_n[br];
    int t = blockIdx.x * 128 + threadIdx.x;
    if (t >= n) return;
    int h = blockIdx.y;
    const float* base = g_SC + (long long)h * S_ * S_ + t;
    float z = 0.f;
    int s = 0;
    for (; s + 4 <= n; s += 4) {
        float v0 = base[(long long)s * S_];
        float v1 = base[(long long)(s + 1) * S_];
        float v2 = base[(long long)(s + 2) * S_];
        float v3 = base[(long long)(s + 3) * S_];
        z += (v0 + v1) + (v2 + v3);
    }
    for (; s < n; s++) z += base[(long long)s * S_];
    g_iZ[h * S_ + t] = 1.f / z;
}

// Vc[h][t][o] *= iZ[h][t]  (replaces staging-time scaling)
__global__ void scaleV(int br)
{
    int id = blockIdx.x * 256 + threadIdx.x;
    if (id >= H_ * S_ * D2_) return;
    int h = id / (S_ * D2_);
    int r = id - h * (S_ * D2_);
    int t = r / D2_;
    if (t < g_n[br]) g_Vc[id] *= g_iZ[h * S_ + t];
}

__global__ void featpart(const float* __restrict__ fw, int br)
{
    int n = g_n[br];
    int j = blockIdx.x;
    int ch = blockIdx.y;
    int per = (n + 7) / 8;
    int s0 = ch * per;
    int s1 = s0 + per; if (s1 > n) s1 = n;
    if (s0 > n) s0 = n;
    float acc = 0.f;
    const float* base = fw + (long long)j * (S_ * D2_);
    for (long long e = (long long)s0 * D2_ + threadIdx.x; e < (long long)s1 * D2_; e += 256)
        acc += g_mh[e] * base[e];
    __shared__ float red[8];
#pragma unroll
    for (int o = 16; o; o >>= 1) acc += __shfl_xor_sync(0xffffffffu, acc, o);
    if ((threadIdx.x & 31) == 0) red[threadIdx.x >> 5] = acc;
    __syncthreads();
    if (threadIdx.x < 8) {
        float v = red[threadIdx.x];
#pragma unroll
        for (int o = 4; o; o >>= 1) v += __shfl_xor_sync(0x000000ffu, v, o);
        if (threadIdx.x == 0) g_fp[(br * 8 + ch) * D2_ + j] = v;
    }
}

__global__ void finalize(const float* __restrict__ fb, float* __restrict__ out)
{
    int i = blockIdx.x * 256 + threadIdx.x;
    if (i >= 400) return;
    int br = i / 200, j = i - br * 200;
    float a = fb[j];
    for (int c = 0; c < 8; c++) a += g_fp[(br * 8 + c) * D2_ + j];
    out[i] = a;
}

// --------------------------------- launcher --------------------------------
extern "C" void kernel_launch(void* const* d_in, const int* in_sizes, int n_in,
                              void* d_out, int out_size)
{
    const int*   rsent = (const int*)d_in[0];
    const int*   body  = (const int*)d_in[1];
    const float* emb   = (const float*)d_in[2];
    const float* wihf  = (const float*)d_in[3];
    const float* whhf  = (const float*)d_in[4];
    const float* bihf  = (const float*)d_in[5];
    const float* bhhf  = (const float*)d_in[6];
    const float* wihb  = (const float*)d_in[7];
    const float* whhb  = (const float*)d_in[8];
    const float* bihb  = (const float*)d_in[9];
    const float* bhhb  = (const float*)d_in[10];
    const float* simw  = (const float*)d_in[11];
    const float* simb  = (const float*)d_in[12];
    const float* qw    = (const float*)d_in[13];
    const float* qb    = (const float*)d_in[14];
    const float* kw    = (const float*)d_in[15];
    const float* kb    = (const float*)d_in[16];
    const float* vw    = (const float*)d_in[17];
    const float* vb    = (const float*)d_in[18];
    const float* cw    = (const float*)d_in[19];
    const float* cb    = (const float*)d_in[20];
    const float* fw    = (const float*)d_in[21];
    const float* fb    = (const float*)d_in[22];
    float* out = (float*)d_out;

    float *pEW, *pAtt, *pQa, *pKa, *pVa, *pQc, *pKc, *pVc, *pSC, *pCat, *pMh;
    cudaGetSymbolAddress((void**)&pEW, g_EW);
    cudaGetSymbolAddress((void**)&pAtt, g_att);
    cudaGetSymbolAddress((void**)&pQa, g_Qa);
    cudaGetSymbolAddress((void**)&pKa, g_Ka);
    cudaGetSymbolAddress((void**)&pVa, g_Va);
    cudaGetSymbolAddress((void**)&pQc, g_Qc);
    cudaGetSymbolAddress((void**)&pKc, g_Kc);
    cudaGetSymbolAddress((void**)&pVc, g_Vc);
    cudaGetSymbolAddress((void**)&pSC, g_SC);
    cudaGetSymbolAddress((void**)&pCat, g_cat);
    cudaGetSymbolAddress((void**)&pMh, g_mh);

    // EW = emb @ w_ih^T (TF32)
    dim3 ge(7, 391, 1);
    tgemm<<<ge, 256>>>(emb, 300, 0, wihf, 300, 0, 1, pEW,       800, 0,
                       V_, 400, 300, nullptr, 0, -1, 0, 0, 0, 0, 0);
    tgemm<<<ge, 256>>>(emb, 300, 0, wihb, 300, 0, 1, pEW + 400, 800, 0,
                       V_, 400, 300, nullptr, 0, -1, 0, 0, 0, 0, 0);

    const int SMEM_LSTM = (40000 + 3400 + 400) * 4 + RPB * 4;
    cudaFuncSetAttribute(lstm_all, cudaFuncAttributeMaxDynamicSharedMemorySize, SMEM_LSTM);
    lstm_all<<<dim3(74, 2), 256, SMEM_LSTM>>>(rsent, body, whhf, whhb,
                                              bihf, bhhf, bihb, bhhb);

    hv_k<<<7, 1024>>>(simw);
    logits_k<<<256, 256>>>(simb);
    softpart<<<1, 1024>>>();
    attend_k<<<1600, 256>>>();

    // Q/K/V on full attend, h-batched (z=8)
    dim3 gq(4, 16, 8);
    tgemm<<<gq, 256>>>(pAtt, 200, 0, qw, 200, 40000LL, 1, pQa, 200, 409600LL,
                       S_, 200, 200, qb, 200, -1, 0, 0, 0, 0, 0);
    tgemm<<<gq, 256>>>(pAtt, 200, 0, kw, 200, 40000LL, 1, pKa, 200, 409600LL,
                       S_, 200, 200, kb, 200, -1, 0, 0, 0, 0, 0);
    tgemm<<<gq, 256>>>(pAtt, 200, 0, vw, 200, 40000LL, 1, pVa, 200, 409600LL,
                       S_, 200, 200, vb, 200, -1, 0, 0, 0, 0, 0);

    for (int br = 0; br < 2; br++) {
        compact<<<2048, 192>>>(br);

        // E[h,s,t] = exp(epi(Qc.Kc)) written directly by the GEMM epilogue
        dim3 gs(32, 16, 8);
        tgemm<<<gs, 256>>>(pQc, 200, 409600LL, pKc, 200, 409600LL, 1,
                           pSC, 2048, 4194304LL, S_, S_, 200,
                           nullptr, 0, br, 1, 1, 0, (br == 0) ? 4 : 3, 0);

        colsum<<<dim3(16, 8), 128>>>(br);
        scaleV<<<12800, 256>>>(br);

        // out = E @ (iZ*V): A zfilled past n via staging clamp
        dim3 go(4, 16, 8);
        tgemm<<<go, 256>>>(pSC, 2048, 4194304LL, pVc, 200, 409600LL, 0,
                           pCat, 1600, 200LL, S_, 200, S_,
                           nullptr, 0, br, 1, 0, 1, 0, 1);

        dim3 gm(4, 16, 1);
        tgemm<<<gm, 256>>>(pCat, 1600, 0, cw, 1600, 0, 1, pMh, 200, 0,
                           S_, 200, 1600, cb, 0, br, 1, 0, 0, 0, 0);

        featpart<<<dim3(200, 8), 256>>>(fw, br);
    }

    finalize<<<2, 256>>>(fb, out);
}

// round 16
// speedup vs baseline: 2.7458x; 1.2593x over previous
#include <cuda_runtime.h>
#include <math.h>

#define NB 2049
#define S_ 2048
#define W_ 64
#define D_ 300
#define M_ 100
#define H_ 8
#define D2_ 200
#define V_ 50000
#define RSQ 0.07071067811865475f   // 1/sqrt(200)

#define RPB 28                     // rows per LSTM block
#define RH 14                      // rows per thread-half

// ----------------------------- device scratch ------------------------------
__device__ float g_EW[V_ * 800];          // emb @ [w_ih_f | w_ih_b]^T
__device__ float g_embR[V_ * 300];        // tf32-rounded emb
__device__ float g_wihR[800 * 300];       // tf32-rounded [wihf; wihb]
__device__ float g_qwR[H_ * D2_ * D2_];
__device__ float g_kwR[H_ * D2_ * D2_];
__device__ float g_vwR[H_ * D2_ * D2_];
__device__ float g_cwR[D2_ * 1600];
__device__ float g_hid[NB * D2_];         // [h_f | h_b]
__device__ float g_hv[D2_];
__device__ float g_logit[S_];
__device__ float g_prob[S_];
__device__ float g_att[S_ * D2_];
__device__ float g_Qa[H_ * S_ * D2_];
__device__ float g_Ka[H_ * S_ * D2_];
__device__ float g_Va[H_ * S_ * D2_];
__device__ float g_Qc[H_ * S_ * D2_];
__device__ float g_Kc[H_ * S_ * D2_];
__device__ float g_Vc[H_ * S_ * D2_];
__device__ float g_SC[33554432];          // 8 * 2048 * 2048: E = exp(scores)
__device__ float g_iZ[H_ * S_];
__device__ float g_cat[S_ * H_ * D2_];    // out in cat layout [s][h*200+o]
__device__ float g_mh[S_ * D2_];
__device__ float g_fp[2 * 8 * D2_];
__device__ int   g_idx[2][S_];
__device__ int   g_n[2];

__device__ __forceinline__ unsigned f2tf(float v) {
    unsigned r; asm("cvt.rna.tf32.f32 %0, %1;" : "=r"(r) : "f"(v)); return r;
}
__device__ __forceinline__ float tfr(float v) {
    return __uint_as_float(f2tf(v));
}
// exp(x) for |x| < 0.3 : degree-4 Taylor (FMA pipe, avoids MUFU)
__device__ __forceinline__ float pexp(float x) {
    return 1.f + x * (1.f + x * (0.5f + x * (0.16666667f + x * 0.041666668f)));
}

__device__ __forceinline__ unsigned sptr(const void* p) {
    return (unsigned)__cvta_generic_to_shared(p);
}
__device__ __forceinline__ void cpa16(unsigned dst, const void* src, int bytes) {
    asm volatile("cp.async.cg.shared.global [%0], [%1], 16, %2;\n"
                 :: "r"(dst), "l"(src), "r"(bytes));
}
__device__ __forceinline__ void cpa_commit() {
    asm volatile("cp.async.commit_group;\n" ::: "memory");
}
__device__ __forceinline__ void cpa_wait0() {
    asm volatile("cp.async.wait_group 0;\n" ::: "memory");
}

// --------- TF32 tensor GEMM, cp.async double-buffered, BK=32 ---------------
// All operands must be pre-rounded to tf32 (RNA) by producers.
// C[M,N] = A[M,K]*op(B) (+bias). transB: B is (N,K). limBr>=0: lim=g_n[limBr];
// limRows/limCols skip tiles; capK caps K. epi: 1 v*RSQ; 2 (1-v)*RSQ;
// 3 pexp(v*RSQ); 4 pexp((1-v)*RSQ). aClampK: zfill A cols with k>=lim.
// roundC: round stored C to tf32 (for C feeding another tgemm).
#define BM 128
#define BN 64
#define BK 32
#define A_STR 36          // [m][k] row stride
#define BT_STR 36         // transB: [n][k] row stride
#define BN_STR 72         // noT:    [k][n] row stride
#define A_BUF 4608        // 128*36
#define B_BUF 2304        // 64*36 == 32*72
#define B_BASE 9216       // 2*A_BUF

__global__ void __launch_bounds__(256)
tgemm(const float* __restrict__ A, int lda, long long sA,
      const float* __restrict__ B, int ldb, long long sB, int transB,
      float* __restrict__ C, int ldc, long long sC,
      int M, int N, int K,
      const float* __restrict__ bias, int sBias,
      int limBr, int limRows, int limCols, int capK, int epi,
      int aClampK, int roundC)
{
    extern __shared__ float dsh[];
    int bz = blockIdx.z;
    int m0 = blockIdx.y * BM;
    int n0 = blockIdx.x * BN;
    int lim = 0x7fffffff;
    if (limBr >= 0) {
        lim = g_n[limBr];
        if (limRows && m0 >= lim) return;
        if (limCols && n0 >= lim) return;
        if (capK) { int kc = (lim + 15) & ~15; if (kc < K) K = kc; }
    }
    int limK = aClampK ? (lim < K ? lim : K) : K;
    A += (long long)bz * sA;
    B += (long long)bz * sB;
    C += (long long)bz * sC;

    int tid = threadIdx.x;            // 256 threads = 8 warps (4m x 2n)
    int lane = tid & 31;
    int wrp = tid >> 5;
    int wm = (wrp & 3) * 32;
    int wn = (wrp >> 2) * 32;
    int grp = lane >> 2;
    int four = lane & 3;

    float acc[2][4][4];
#pragma unroll
    for (int i = 0; i < 2; i++)
#pragma unroll
        for (int j = 0; j < 4; j++)
#pragma unroll
            for (int q = 0; q < 4; q++) acc[i][j][q] = 0.f;

    unsigned shb = sptr(dsh);
    unsigned asb[2] = { shb, shb + A_BUF * 4 };
    unsigned bsb[2] = { shb + B_BASE * 4, shb + (B_BASE + B_BUF) * 4 };

    auto stage = [&](int k0v, int b) {
        // A: 128 x 32 as [m][k]: 1024 16B chunks, 4 per thread
#pragma unroll
        for (int i = 0; i < 4; i++) {
            int e = tid + i * 256;
            int m = e >> 3, kc = (e & 7) * 4;
            int gm = m0 + m, gk = k0v + kc;
            int rem = limK - gk; if (rem > 4) rem = 4; if (rem < 0) rem = 0;
            int bytes = (gm < M) ? rem * 4 : 0;
            cpa16(asb[b] + (m * A_STR + kc) * 4,
                  A + (long long)(gm < M ? gm : 0) * lda + (gk < K ? gk : 0), bytes);
        }
        if (transB) {
            // B: 64 x 32 as [n][k]: 512 chunks, 2 per thread
#pragma unroll
            for (int i = 0; i < 2; i++) {
                int e = tid + i * 256;
                int n = e >> 3, kc = (e & 7) * 4;
                int gn = n0 + n, gk = k0v + kc;
                int rem = K - gk; if (rem > 4) rem = 4; if (rem < 0) rem = 0;
                int bytes = (gn < N) ? rem * 4 : 0;
                cpa16(bsb[b] + (n * BT_STR + kc) * 4,
                      B + (long long)(gn < N ? gn : 0) * ldb + (gk < K ? gk : 0), bytes);
            }
        } else {
            // B: 32 x 64 as [k][n]: 512 chunks, 2 per thread
#pragma unroll
            for (int i = 0; i < 2; i++) {
                int e = tid + i * 256;
                int k = e >> 4, nc = (e & 15) * 4;
                int gk = k0v + k, gn = n0 + nc;
                int rem = N - gn; if (rem > 4) rem = 4; if (rem < 0) rem = 0;
                int bytes = (gk < K) ? rem * 4 : 0;
                cpa16(bsb[b] + (k * BN_STR + nc) * 4,
                      B + (long long)(gk < K ? gk : 0) * ldb + (rem ? gn : 0), bytes);
            }
        }
    };

    stage(0, 0);
    cpa_commit();

    int buf = 0;
    for (int k0v = 0; k0v < K; k0v += BK) {
        cpa_wait0();
        __syncthreads();
        int kn = k0v + BK;
        if (kn < K) { stage(kn, buf ^ 1); cpa_commit(); }

        const float* Ab = dsh + buf * A_BUF;
        const float* Bb = dsh + B_BASE + buf * B_BUF;
#pragma unroll
        for (int kk = 0; kk < BK; kk += 8) {
            unsigned a[2][4];
#pragma unroll
            for (int ma = 0; ma < 2; ma++) {
                int mb = wm + ma * 16 + grp;
                a[ma][0] = __float_as_uint(Ab[mb * A_STR + kk + four]);
                a[ma][1] = __float_as_uint(Ab[(mb + 8) * A_STR + kk + four]);
                a[ma][2] = __float_as_uint(Ab[mb * A_STR + kk + 4 + four]);
                a[ma][3] = __float_as_uint(Ab[(mb + 8) * A_STR + kk + 4 + four]);
            }
#pragma unroll
            for (int na = 0; na < 4; na++) {
                int nb = wn + na * 8 + grp;
                unsigned b0, b1;
                if (transB) {
                    b0 = __float_as_uint(Bb[nb * BT_STR + kk + four]);
                    b1 = __float_as_uint(Bb[nb * BT_STR + kk + 4 + four]);
                } else {
                    b0 = __float_as_uint(Bb[(kk + four) * BN_STR + nb]);
                    b1 = __float_as_uint(Bb[(kk + 4 + four) * BN_STR + nb]);
                }
#pragma unroll
                for (int ma = 0; ma < 2; ma++) {
                    asm("mma.sync.aligned.m16n8k8.row.col.f32.tf32.tf32.f32 "
                        "{%0,%1,%2,%3}, {%4,%5,%6,%7}, {%8,%9}, {%0,%1,%2,%3};"
                        : "+f"(acc[ma][na][0]), "+f"(acc[ma][na][1]),
                          "+f"(acc[ma][na][2]), "+f"(acc[ma][na][3])
                        : "r"(a[ma][0]), "r"(a[ma][1]), "r"(a[ma][2]), "r"(a[ma][3]),
                          "r"(b0), "r"(b1));
                }
            }
        }
        buf ^= 1;
    }

#pragma unroll
    for (int ma = 0; ma < 2; ma++) {
#pragma unroll
        for (int na = 0; na < 4; na++) {
            int gmb = m0 + wm + ma * 16 + grp;
            int gnb = n0 + wn + na * 8 + 2 * four;
#pragma unroll
            for (int q = 0; q < 4; q++) {
                int gm = gmb + (q >> 1) * 8;
                int gn = gnb + (q & 1);
                if (gm >= M || gn >= N) continue;
                float v = acc[ma][na][q];
                if (bias) v += bias[bz * sBias + gn];
                if (epi == 1) v *= RSQ;
                else if (epi == 2) v = (1.f - v) * RSQ;
                else if (epi == 3) v = pexp(v * RSQ);
                else if (epi == 4) v = pexp((1.f - v) * RSQ);
                if (roundC) v = tfr(v);
                C[(long long)gm * ldc + gn] = v;
            }
        }
    }
}

#define TG_SMEM ((2 * A_BUF + 2 * B_BUF) * 4)

// -------------------------- tf32 round-copy pass ----------------------------
__global__ void roundcp(const float* __restrict__ src, float* __restrict__ dst, int n)
{
    int i = blockIdx.x * 256 + threadIdx.x;
    if (i < n) dst[i] = tfr(src[i]);
}

// ------------------------- fused all-timestep LSTM --------------------------
__global__ void __launch_bounds__(256, 1)
lstm_all(const int* __restrict__ rsent, const int* __restrict__ body,
         const float* __restrict__ whf, const float* __restrict__ whb,
         const float* __restrict__ bihf, const float* __restrict__ bhhf,
         const float* __restrict__ bihb, const float* __restrict__ bhhb)
{
    extern __shared__ float sh[];
    float* Wg  = sh;                    // [100][100] float4 gates (40000 floats)
    float* hT  = sh + 40000;            // [100][34]
    float* bcs = sh + 43400;            // [400]
    int*   toks = (int*)(sh + 43800);   // [28]

    int dir = blockIdx.y;
    int n0 = blockIdx.x * RPB;
    int tid = threadIdx.x;

    const float* wh = dir ? whb : whf;
    const float* bi = dir ? bihb : bihf;
    const float* bh = dir ? bhhb : bhhf;

    // Wg[m*400 + m2*4 + gate] = wh[(gate*100 + m2)*100 + m]
    for (int e = tid; e < 40000; e += 256) {
        int j = e / 100, m = e - j * 100;
        int gate = j / 100, m2s = j - gate * 100;
        Wg[m * 400 + m2s * 4 + gate] = wh[e];
    }
    for (int j = tid; j < 400; j += 256) bcs[j] = bi[j] + bh[j];
    for (int e = tid; e < 3400; e += 256) hT[e] = 0.f;

    int m2 = tid & 127;
    int half = tid >> 7;
    int rbase = half * RH;
    bool act = (m2 < 100);

    if (tid < RPB) {
        int w0 = dir ? 63 : 0;
        int n = n0 + tid;
        if (n >= NB) n = NB - 1;
        toks[tid] = (n == 0) ? rsent[w0] : body[(n - 1) * W_ + w0];
    }
    __syncthreads();

    float bj[4];
    if (act) {
#pragma unroll
        for (int jo = 0; jo < 4; jo++) bj[jo] = bcs[m2 + jo * 100];
    }

    float c[RH];
#pragma unroll
    for (int r = 0; r < RH; r++) c[r] = 0.f;

    for (int t = 0; t < 64; t++) {
        float ew[4][RH];
        float acc[4][RH];
        if (act) {
#pragma unroll
            for (int jo = 0; jo < 4; jo++) {
                int j = m2 + jo * 100;
#pragma unroll
                for (int r = 0; r < RH; r++)
                    ew[jo][r] = g_EW[(long long)toks[rbase + r] * 800 + dir * 400 + j];
            }
#pragma unroll
            for (int jo = 0; jo < 4; jo++)
#pragma unroll
                for (int r = 0; r < RH; r++) acc[jo][r] = 0.f;

            for (int m = 0; m < 100; m++) {
                float4 w = *reinterpret_cast<const float4*>(&Wg[m * 400 + m2 * 4]);
                const float2* hp = reinterpret_cast<const float2*>(&hT[m * 34 + rbase]);
#pragma unroll
                for (int p = 0; p < 7; p++) {
                    float2 hv = hp[p];
                    acc[0][2 * p]     += w.x * hv.x;
                    acc[0][2 * p + 1] += w.x * hv.y;
                    acc[1][2 * p]     += w.y * hv.x;
                    acc[1][2 * p + 1] += w.y * hv.y;
                    acc[2][2 * p]     += w.z * hv.x;
                    acc[2][2 * p + 1] += w.z * hv.y;
                    acc[3][2 * p]     += w.w * hv.x;
                    acc[3][2 * p + 1] += w.w * hv.y;
                }
            }
        }
        __syncthreads();
        if (act) {
#pragma unroll
            for (int r = 0; r < RH; r++) {
                float gi = acc[0][r] + ew[0][r] + bj[0];
                float gf = acc[1][r] + ew[1][r] + bj[1];
                float gg = acc[2][r] + ew[2][r] + bj[2];
                float go = acc[3][r] + ew[3][r] + bj[3];
                float fi = 1.f / (1.f + expf(-gi));
                float ff = 1.f / (1.f + expf(-gf));
                float fo = 1.f / (1.f + expf(-go));
                c[r] = ff * c[r] + fi * tanhf(gg);
                hT[m2 * 34 + rbase + r] = fo * tanhf(c[r]);
            }
        }
        int tn = t + 1;
        if (tn < 64 && tid < RPB) {
            int w = dir ? (63 - tn) : tn;
            int n = n0 + tid;
            if (n >= NB) n = NB - 1;
            toks[tid] = (n == 0) ? rsent[w] : body[(n - 1) * W_ + w];
        }
        __syncthreads();
    }

    if (act) {
#pragma unroll
        for (int r = 0; r < RH; r++) {
            int n = n0 + rbase + r;
            if (n < NB) g_hid[n * D2_ + dir * M_ + m2] = hT[m2 * 34 + rbase + r];
        }
    }
}

// ----------------------------- sim / partition -----------------------------
__global__ void hv_k(const float* __restrict__ simw)
{
    int warp = threadIdx.x >> 5, lane = threadIdx.x & 31;
    int b = blockIdx.x * 32 + warp;
    if (b >= D2_) return;
    float a = 0.f;
    for (int i = lane; i < D2_; i += 32) a += g_hid[i] * simw[i * D2_ + b];
#pragma unroll
    for (int o = 16; o; o >>= 1) a += __shfl_down_sync(0xffffffffu, a, o);
    if (lane == 0) g_hv[b] = a;
}

__global__ void logits_k(const float* __restrict__ simb)
{
    __shared__ float hv[D2_];
    int tid = threadIdx.x;
    if (tid < D2_) hv[tid] = g_hv[tid];
    __syncthreads();
    int warp = tid >> 5, lane = tid & 31;
    int s = blockIdx.x * 8 + warp;
    const float* row = g_hid + (long long)(s + 1) * D2_;
    float a = 0.f;
    for (int b = lane; b < D2_; b += 32) a += hv[b] * row[b];
#pragma unroll
    for (int o = 16; o; o >>= 1) a += __shfl_down_sync(0xffffffffu, a, o);
    if (lane == 0) g_logit[s] = a + simb[0];
}

__global__ void softpart()
{
    __shared__ float sg[S_];
    __shared__ float redm[32];
    __shared__ float reds[32];
    __shared__ int cnt[1024];
    int tid = threadIdx.x;           // 1024
    for (int s = tid; s < S_; s += 1024) {
        float l = g_logit[s];
        sg[s] = 1.f / (1.f + expf(-l));
    }
    __syncthreads();
    float m = fmaxf(sg[tid], sg[tid + 1024]);
#pragma unroll
    for (int o = 16; o; o >>= 1) m = fmaxf(m, __shfl_xor_sync(0xffffffffu, m, o));
    if ((tid & 31) == 0) redm[tid >> 5] = m;
    __syncthreads();
    if (tid < 32) {
        float v = redm[tid];
#pragma unroll
        for (int o = 16; o; o >>= 1) v = fmaxf(v, __shfl_xor_sync(0xffffffffu, v, o));
        if (tid == 0) redm[0] = v;
    }
    __syncthreads();
    float mx = redm[0];
    float z = expf(sg[tid] - mx) + expf(sg[tid + 1024] - mx);
#pragma unroll
    for (int o = 16; o; o >>= 1) z += __shfl_xor_sync(0xffffffffu, z, o);
    if ((tid & 31) == 0) reds[tid >> 5] = z;
    __syncthreads();
    if (tid < 32) {
        float v = reds[tid];
#pragma unroll
        for (int o = 16; o; o >>= 1) v += __shfl_xor_sync(0xffffffffu, v, o);
        if (tid == 0) reds[0] = v;
    }
    __syncthreads();
    float invZ = 1.f / reds[0];
    for (int s = tid; s < S_; s += 1024) g_prob[s] = expf(sg[s] - mx) * invZ;

    int a = (sg[2 * tid] >= 0.5f) ? 1 : 0;
    int b = (sg[2 * tid + 1] >= 0.5f) ? 1 : 0;
    cnt[tid] = a + b;
    __syncthreads();
    for (int off = 1; off < 1024; off <<= 1) {
        int v = cnt[tid];
        int u = (tid >= off) ? cnt[tid - off] : 0;
        __syncthreads();
        cnt[tid] = v + u;
        __syncthreads();
    }
    int pre = (tid > 0) ? cnt[tid - 1] : 0;
    int tot = cnt[1023];
    int s0 = 2 * tid, s1 = 2 * tid + 1;
    if (a) g_idx[0][pre] = s0; else g_idx[1][s0 - pre] = s0;
    int pre1 = pre + a;
    if (b) g_idx[0][pre1] = s1; else g_idx[1][s1 - pre1] = s1;
    if (tid == 0) { g_n[0] = tot; g_n[1] = S_ - tot; }
}

__global__ void attend_k()
{
    int e = blockIdx.x * 256 + threadIdx.x;
    if (e >= S_ * D2_) return;
    int s = e / D2_;
    g_att[e] = tfr(g_prob[s] * g_hid[e + D2_]);
}

// -------------------------- branch-local kernels ---------------------------
__global__ void compact(int br)
{
    int p = blockIdx.x;
    if (p >= g_n[br]) return;
    int src = g_idx[br][p];
    for (int e = threadIdx.x; e < H_ * D2_; e += 192) {
        int h = e / D2_, o = e - h * D2_;
        long long di = (long long)h * (S_ * D2_) + (long long)p * D2_ + o;
        long long si = (long long)h * (S_ * D2_) + (long long)src * D2_ + o;
        g_Qc[di] = g_Qa[si];
        g_Kc[di] = g_Ka[si];
        g_Vc[di] = g_Va[si];
    }
}

// column sums of E (no max-subtraction needed: |scores·RSQ| << 1)
__global__ void colsum(int br)
{
    int n = g_n[br];
    int t = blockIdx.x * 128 + threadIdx.x;
    if (t >= n) return;
    int h = blockIdx.y;
    const float* base = g_SC + (long long)h * S_ * S_ + t;
    float z = 0.f;
    int s = 0;
    for (; s + 4 <= n; s += 4) {
        float v0 = base[(long long)s * S_];
        float v1 = base[(long long)(s + 1) * S_];
        float v2 = base[(long long)(s + 2) * S_];
        float v3 = base[(long long)(s + 3) * S_];
        z += (v0 + v1) + (v2 + v3);
    }
    for (; s < n; s++) z += base[(long long)s * S_];
    g_iZ[h * S_ + t] = 1.f / z;
}

// Vc[h][t][o] *= iZ[h][t], rounded to tf32 (feeds out-gemm)
__global__ void scaleV(int br)
{
    int id = blockIdx.x * 256 + threadIdx.x;
    if (id >= H_ * S_ * D2_) return;
    int h = id / (S_ * D2_);
    int r = id - h * (S_ * D2_);
    int t = r / D2_;
    if (t < g_n[br]) g_Vc[id] = tfr(g_Vc[id] * g_iZ[h * S_ + t]);
}

__global__ void featpart(const float* __restrict__ fw, int br)
{
    int n = g_n[br];
    int j = blockIdx.x;
    int ch = blockIdx.y;
    int per = (n + 7) / 8;
    int s0 = ch * per;
    int s1 = s0 + per; if (s1 > n) s1 = n;
    if (s0 > n) s0 = n;
    float acc = 0.f;
    const float* base = fw + (long long)j * (S_ * D2_);
    for (long long e = (long long)s0 * D2_ + threadIdx.x; e < (long long)s1 * D2_; e += 256)
        acc += g_mh[e] * base[e];
    __shared__ float red[8];
#pragma unroll
    for (int o = 16; o; o >>= 1) acc += __shfl_xor_sync(0xffffffffu, acc, o);
    if ((threadIdx.x & 31) == 0) red[threadIdx.x >> 5] = acc;
    __syncthreads();
    if (threadIdx.x < 8) {
        float v = red[threadIdx.x];
#pragma unroll
        for (int o = 4; o; o >>= 1) v += __shfl_xor_sync(0x000000ffu, v, o);
        if (threadIdx.x == 0) g_fp[(br * 8 + ch) * D2_ + j] = v;
    }
}

__global__ void finalize(const float* __restrict__ fb, float* __restrict__ out)
{
    int i = blockIdx.x * 256 + threadIdx.x;
    if (i >= 400) return;
    int br = i / 200, j = i - br * 200;
    float a = fb[j];
    for (int c = 0; c < 8; c++) a += g_fp[(br * 8 + c) * D2_ + j];
    out[i] = a;
}

// --------------------------------- launcher --------------------------------
extern "C" void kernel_launch(void* const* d_in, const int* in_sizes, int n_in,
                              void* d_out, int out_size)
{
    const int*   rsent = (const int*)d_in[0];
    const int*   body  = (const int*)d_in[1];
    const float* emb   = (const float*)d_in[2];
    const float* wihf  = (const float*)d_in[3];
    const float* whhf  = (const float*)d_in[4];
    const float* bihf  = (const float*)d_in[5];
    const float* bhhf  = (const float*)d_in[6];
    const float* wihb  = (const float*)d_in[7];
    const float* whhb  = (const float*)d_in[8];
    const float* bihb  = (const float*)d_in[9];
    const float* bhhb  = (const float*)d_in[10];
    const float* simw  = (const float*)d_in[11];
    const float* simb  = (const float*)d_in[12];
    const float* qw    = (const float*)d_in[13];
    const float* qb    = (const float*)d_in[14];
    const float* kw    = (const float*)d_in[15];
    const float* kb    = (const float*)d_in[16];
    const float* vw    = (const float*)d_in[17];
    const float* vb    = (const float*)d_in[18];
    const float* cw    = (const float*)d_in[19];
    const float* cb    = (const float*)d_in[20];
    const float* fw    = (const float*)d_in[21];
    const float* fb    = (const float*)d_in[22];
    float* out = (float*)d_out;

    float *pEW, *pEmbR, *pWihR, *pQwR, *pKwR, *pVwR, *pCwR;
    float *pAtt, *pQa, *pKa, *pVa, *pQc, *pKc, *pVc, *pSC, *pCat, *pMh;
    cudaGetSymbolAddress((void**)&pEW, g_EW);
    cudaGetSymbolAddress((void**)&pEmbR, g_embR);
    cudaGetSymbolAddress((void**)&pWihR, g_wihR);
    cudaGetSymbolAddress((void**)&pQwR, g_qwR);
    cudaGetSymbolAddress((void**)&pKwR, g_kwR);
    cudaGetSymbolAddress((void**)&pVwR, g_vwR);
    cudaGetSymbolAddress((void**)&pCwR, g_cwR);
    cudaGetSymbolAddress((void**)&pAtt, g_att);
    cudaGetSymbolAddress((void**)&pQa, g_Qa);
    cudaGetSymbolAddress((void**)&pKa, g_Ka);
    cudaGetSymbolAddress((void**)&pVa, g_Va);
    cudaGetSymbolAddress((void**)&pQc, g_Qc);
    cudaGetSymbolAddress((void**)&pKc, g_Kc);
    cudaGetSymbolAddress((void**)&pVc, g_Vc);
    cudaGetSymbolAddress((void**)&pSC, g_SC);
    cudaGetSymbolAddress((void**)&pCat, g_cat);
    cudaGetSymbolAddress((void**)&pMh, g_mh);

    cudaFuncSetAttribute(tgemm, cudaFuncAttributeMaxDynamicSharedMemorySize, TG_SMEM);

    // ---- tf32 pre-round of external GEMM operands ----
    roundcp<<<58594, 256>>>(emb, pEmbR, V_ * 300);
    roundcp<<<469, 256>>>(wihf, pWihR, 120000);
    roundcp<<<469, 256>>>(wihb, pWihR + 120000, 120000);
    roundcp<<<1250, 256>>>(qw, pQwR, 320000);
    roundcp<<<1250, 256>>>(kw, pKwR, 320000);
    roundcp<<<1250, 256>>>(vw, pVwR, 320000);
    roundcp<<<1250, 256>>>(cw, pCwR, 320000);

    // EW = embR @ wihR^T  (fused both directions, N=800)
    dim3 ge(13, 391, 1);
    tgemm<<<ge, 256, TG_SMEM>>>(pEmbR, 300, 0, pWihR, 300, 0, 1, pEW, 800, 0,
                                V_, 800, 300, nullptr, 0, -1, 0, 0, 0, 0, 0, 0);

    const int SMEM_LSTM = (40000 + 3400 + 400) * 4 + RPB * 4;
    cudaFuncSetAttribute(lstm_all, cudaFuncAttributeMaxDynamicSharedMemorySize, SMEM_LSTM);
    lstm_all<<<dim3(74, 2), 256, SMEM_LSTM>>>(rsent, body, whhf, whhb,
                                              bihf, bhhf, bihb, bhhb);

    hv_k<<<7, 1024>>>(simw);
    logits_k<<<256, 256>>>(simb);
    softpart<<<1, 1024>>>();
    attend_k<<<1600, 256>>>();

    // Q/K/V on full attend, h-batched (z=8); Q,K rounded for scores gemm
    dim3 gq(4, 16, 8);
    tgemm<<<gq, 256, TG_SMEM>>>(pAtt, 200, 0, pQwR, 200, 40000LL, 1, pQa, 200, 409600LL,
                                S_, 200, 200, qb, 200, -1, 0, 0, 0, 0, 0, 1);
    tgemm<<<gq, 256, TG_SMEM>>>(pAtt, 200, 0, pKwR, 200, 40000LL, 1, pKa, 200, 409600LL,
                                S_, 200, 200, kb, 200, -1, 0, 0, 0, 0, 0, 1);
    tgemm<<<gq, 256, TG_SMEM>>>(pAtt, 200, 0, pVwR, 200, 40000LL, 1, pVa, 200, 409600LL,
                                S_, 200, 200, vb, 200, -1, 0, 0, 0, 0, 0, 0);

    for (int br = 0; br < 2; br++) {
        compact<<<2048, 192>>>(br);

        // E[h,s,t] = exp(epi(Qc.Kc)), rounded (feeds out-gemm)
        dim3 gs(32, 16, 8);
        tgemm<<<gs, 256, TG_SMEM>>>(pQc, 200, 409600LL, pKc, 200, 409600LL, 1,
                                    pSC, 2048, 4194304LL, S_, S_, 200,
                                    nullptr, 0, br, 1, 1, 0, (br == 0) ? 4 : 3, 0, 1);

        colsum<<<dim3(16, 8), 128>>>(br);
        scaleV<<<12800, 256>>>(br);

        // out = E @ (iZ*V): A zfilled past n via staging clamp; cat rounded
        dim3 go(4, 16, 8);
        tgemm<<<go, 256, TG_SMEM>>>(pSC, 2048, 4194304LL, pVc, 200, 409600LL, 0,
                                    pCat, 1600, 200LL, S_, 200, S_,
                                    nullptr, 0, br, 1, 0, 1, 0, 1, 1);

        dim3 gm(4, 16, 1);
        tgemm<<<gm, 256, TG_SMEM>>>(pCat, 1600, 0, pCwR, 1600, 0, 1, pMh, 200, 0,
                                    S_, 200, 1600, cb, 0, br, 1, 0, 0, 0, 0, 0);

        featpart<<<dim3(200, 8), 256>>>(fw, br);
    }

    finalize<<<2, 256>>>(fb, out);
}